// round 4
// baseline (speedup 1.0000x reference)
#include <cuda_runtime.h>
#include <math.h>
#include <stdint.h>

#define NN 100000
#define NE 800000
#define NG 64
#define NT 4
#define D 150
#define HIDN 512
#define PASSES 5
#define NC1 1050      // GEMM1 output cols: 600 (m) + 450 (gh)
#define MLD 1056      // out1 leading dim (padded)
#define GILD 456      // gi leading dim (padded)
#define XLD 152
#define KLD 160       // padded K stride for GEMM A/B operands (zeros in 150..159)

// ---------------- scratch (device globals; no allocation allowed) ----------
__device__ float g_h[(size_t)NN * KLD];
__device__ float g_inc[(size_t)NN * KLD];
__device__ float g_out1[(size_t)NN * MLD];
__device__ float g_gi[(size_t)NN * GILD];
__device__ float g_biasinc[(size_t)NN * D];
__device__ float g_Wbig[NC1 * KLD];
__device__ float g_wih[450 * KLD];
__device__ float g_bias1[NC1];
__device__ int   g_degt[NN * NT];
__device__ int   g_rowptr[NN + 1];
__device__ int   g_cursor[NN];
__device__ int   g_ebase[NE];
__device__ int   g_gstart[NG + 1];
__device__ float g_x[NG * XLD];

// ---------------- fused setup: zero degt, build padded Wbig/wih, bias1 -----
__global__ void setup_weights(const float* __restrict__ We, const float* __restrict__ whh,
                              const float* __restrict__ wih,
                              const float* __restrict__ bhh,
                              float* __restrict__ wbig, float* __restrict__ wihp,
                              float* __restrict__ bias1, int* __restrict__ degt) {
    int idx = blockIdx.x * blockDim.x + threadIdx.x;
    if (idx < NN * NT) { degt[idx] = 0; return; }
    idx -= NN * NT;
    if (idx < NC1 * KLD) {
        int c = idx / KLD, j = idx - c * KLD;
        float v = 0.f;
        if (j < D) v = (c < 600) ? We[c * D + j] : whh[(c - 600) * D + j];
        wbig[idx] = v;
        return;
    }
    idx -= NC1 * KLD;
    if (idx < 450 * KLD) {
        int c = idx / KLD, j = idx - c * KLD;
        wihp[idx] = (j < D) ? wih[c * D + j] : 0.f;
        return;
    }
    idx -= 450 * KLD;
    if (idx < NC1) bias1[idx] = (idx < 600) ? 0.f : bhh[idx - 600];
}

// copy nodes -> g_h (padded) and zero g_inc padding columns
__global__ void copy_h(const float* __restrict__ nodes, float* __restrict__ h,
                       float* __restrict__ inc) {
    int idx = blockIdx.x * blockDim.x + threadIdx.x;
    if (idx < NN * KLD) {
        int node = idx / KLD, c = idx - node * KLD;
        h[idx] = (c < D) ? nodes[node * D + c] : 0.f;
        return;
    }
    idx -= NN * KLD;
    if (idx < NN * (KLD - D)) {
        int node = idx / (KLD - D), c = D + idx % (KLD - D);
        inc[node * KLD + c] = 0.f;
    }
}

__global__ void hist_kernel(const int* __restrict__ dst, const int* __restrict__ etype,
                            int* __restrict__ degt, int E) {
    int e = blockIdx.x * blockDim.x + threadIdx.x;
    if (e < E) atomicAdd(&degt[dst[e] * NT + etype[e]], 1);
}

__global__ void biasinc_kernel(const int* __restrict__ degt, const float* __restrict__ be,
                               float* __restrict__ biasinc, int n_nodes) {
    int idx = blockIdx.x * blockDim.x + threadIdx.x;
    if (idx >= n_nodes * D) return;
    int node = idx / D, i = idx - node * D;
    float s = 0.f;
#pragma unroll
    for (int t = 0; t < NT; ++t)
        s += (float)degt[node * NT + t] * be[t * D + i];
    biasinc[idx] = s;
}

// single-block exclusive scan; also writes cursor copy
__global__ void scan_kernel(const int* __restrict__ degt, int* __restrict__ rowptr,
                            int* __restrict__ cursor, int n) {
    __shared__ int warp_tot[32];
    __shared__ int carry_s;
    int tid = threadIdx.x;
    int lane = tid & 31, wid = tid >> 5;
    if (tid == 0) carry_s = 0;
    __syncthreads();
    for (int base = 0; base < n; base += 1024) {
        int idx = base + tid;
        int v = 0;
        if (idx < n)
            v = degt[idx * NT] + degt[idx * NT + 1] + degt[idx * NT + 2] + degt[idx * NT + 3];
        int x = v;
#pragma unroll
        for (int off = 1; off < 32; off <<= 1) {
            int y = __shfl_up_sync(0xffffffffu, x, off);
            if (lane >= off) x += y;
        }
        if (lane == 31) warp_tot[wid] = x;
        __syncthreads();
        if (wid == 0) {
            int w = warp_tot[lane];
            int wx = w;
#pragma unroll
            for (int off = 1; off < 32; off <<= 1) {
                int y = __shfl_up_sync(0xffffffffu, wx, off);
                if (lane >= off) wx += y;
            }
            warp_tot[lane] = wx - w;
        }
        __syncthreads();
        int excl = carry_s + warp_tot[wid] + x - v;
        if (idx < n) { rowptr[idx] = excl; cursor[idx] = excl; }
        __syncthreads();
        if (tid == 1023) carry_s = excl + v;
        __syncthreads();
    }
    if (tid == 0) rowptr[n] = carry_s;
}

__global__ void csr_fill(const int* __restrict__ src, const int* __restrict__ dst,
                         const int* __restrict__ etype, int* __restrict__ cursor,
                         int* __restrict__ ebase, int E) {
    int e = blockIdx.x * blockDim.x + threadIdx.x;
    if (e >= E) return;
    int pos = atomicAdd(&cursor[dst[e]], 1);
    ebase[pos] = src[e] * MLD + etype[e] * D;
}

// ---------------- 3xTF32 tensor-core GEMM ----------------
// C[M,N] = A[M,K]@B[N,K]^T + bias[N], K fixed = 160 (zero padded), lda=ldb=KLD
// Each fp32 split: hi = tf32(x), lo = tf32(x - hi). Product = hi*hi + hi*lo + lo*hi
// (lo*lo dropped: ~2^-22 relative). fp32-level accuracy on the tensor pipe.
#define KC 32
#define KSTEPS 4
#define NCHUNK 5

__device__ __forceinline__ uint32_t f2tf32(float f) {
    uint32_t u;
    asm("cvt.rna.tf32.f32 %0, %1;" : "=r"(u) : "f"(f));
    return u;
}

__device__ __forceinline__ void mma_tf32(float* d, const uint32_t* a, const uint32_t* b) {
    asm volatile(
        "mma.sync.aligned.m16n8k8.row.col.f32.tf32.tf32.f32 "
        "{%0,%1,%2,%3}, {%4,%5,%6,%7}, {%8,%9}, {%0,%1,%2,%3};"
        : "+f"(d[0]), "+f"(d[1]), "+f"(d[2]), "+f"(d[3])
        : "r"(a[0]), "r"(a[1]), "r"(a[2]), "r"(a[3]), "r"(b[0]), "r"(b[1]));
}

#define AIDX(ks, mt, ln, rg) ((((ks) * 8 + (mt)) * 32 + (ln)) * 4 + (rg))
#define BIDX(ks, nt, ln, rg) ((((ks) * 16 + (nt)) * 32 + (ln)) * 2 + (rg))
#define SM_A 4096   // u32 count of one A stage array
#define SM_B 4096

__global__ __launch_bounds__(256) void gemm_3xtf32(
    const float* __restrict__ A,
    const float* __restrict__ B,
    float* __restrict__ C, int ldc,
    int M, int N, const float* __restrict__ bias) {
    extern __shared__ uint32_t sm[];
    uint32_t* As_hi = sm;
    uint32_t* As_lo = sm + SM_A;
    uint32_t* Bs_hi = sm + 2 * SM_A;
    uint32_t* Bs_lo = sm + 2 * SM_A + SM_B;

    int tid = threadIdx.x;
    int lane = tid & 31, wid = tid >> 5;
    int wm = wid & 1, wn = wid >> 1;  // 2x4 warp grid
    int m0 = blockIdx.y * 128, n0 = blockIdx.x * 128;

    float acc[4][4][4];
#pragma unroll
    for (int i = 0; i < 4; ++i)
#pragma unroll
        for (int j = 0; j < 4; ++j)
#pragma unroll
            for (int r = 0; r < 4; ++r) acc[i][j][r] = 0.f;

    int ra = tid >> 1;      // row handled in staging (0..127)
    int qa = tid & 1;       // which 16-col half of the 32-col chunk

    // A staging decomposition
    int a_mt = ra >> 4;
    int a_r = ra & 15;
    int a_lbase = (a_r & 7) * 4;
    int a_rbase = a_r >> 3;
    // B staging decomposition
    int b_nt = ra >> 3;
    int b_lbase = (ra & 7) * 4;

    for (int kc = 0; kc < NCHUNK; ++kc) {
        int k0 = kc * KC;
        // ---- stage A (hi + lo) ----
        {
            int gm = m0 + ra;
            const float4* srcp = (const float4*)(A + (size_t)gm * KLD + k0 + qa * 16);
#pragma unroll
            for (int q = 0; q < 4; ++q) {
                float4 v = make_float4(0.f, 0.f, 0.f, 0.f);
                if (gm < M) v = srcp[q];
                int kk = qa * 16 + q * 4;
                int ks = kk >> 3;
                int reg = a_rbase + (((kk & 7) >= 4) ? 2 : 0);
                int base = AIDX(ks, a_mt, a_lbase, reg);
                uint32_t hx = f2tf32(v.x), hy = f2tf32(v.y);
                uint32_t hz = f2tf32(v.z), hw = f2tf32(v.w);
                As_hi[base + 0]  = hx;
                As_hi[base + 4]  = hy;
                As_hi[base + 8]  = hz;
                As_hi[base + 12] = hw;
                As_lo[base + 0]  = f2tf32(v.x - __uint_as_float(hx));
                As_lo[base + 4]  = f2tf32(v.y - __uint_as_float(hy));
                As_lo[base + 8]  = f2tf32(v.z - __uint_as_float(hz));
                As_lo[base + 12] = f2tf32(v.w - __uint_as_float(hw));
            }
        }
        // ---- stage B (hi + lo) ----
        {
            int gn = n0 + ra;
            const float4* srcp = (const float4*)(B + (size_t)gn * KLD + k0 + qa * 16);
#pragma unroll
            for (int q = 0; q < 4; ++q) {
                float4 v = make_float4(0.f, 0.f, 0.f, 0.f);
                if (gn < N) v = srcp[q];
                int kk = qa * 16 + q * 4;
                int ks = kk >> 3;
                int reg = ((kk & 7) >= 4) ? 1 : 0;
                int base = BIDX(ks, b_nt, b_lbase, reg);
                uint32_t hx = f2tf32(v.x), hy = f2tf32(v.y);
                uint32_t hz = f2tf32(v.z), hw = f2tf32(v.w);
                Bs_hi[base + 0] = hx;
                Bs_hi[base + 2] = hy;
                Bs_hi[base + 4] = hz;
                Bs_hi[base + 6] = hw;
                Bs_lo[base + 0] = f2tf32(v.x - __uint_as_float(hx));
                Bs_lo[base + 2] = f2tf32(v.y - __uint_as_float(hy));
                Bs_lo[base + 4] = f2tf32(v.z - __uint_as_float(hz));
                Bs_lo[base + 6] = f2tf32(v.w - __uint_as_float(hw));
            }
        }
        __syncthreads();
        // ---- compute: 3 MMAs per (mt,nt) per ks ----
#pragma unroll
        for (int ks = 0; ks < KSTEPS; ++ks) {
            uint32_t ah[4][4], al[4][4];
            uint32_t bh[4][2], bl[4][2];
#pragma unroll
            for (int mt = 0; mt < 4; ++mt) {
                uint4 t = *(const uint4*)&As_hi[AIDX(ks, wm * 4 + mt, lane, 0)];
                ah[mt][0] = t.x; ah[mt][1] = t.y; ah[mt][2] = t.z; ah[mt][3] = t.w;
                uint4 u = *(const uint4*)&As_lo[AIDX(ks, wm * 4 + mt, lane, 0)];
                al[mt][0] = u.x; al[mt][1] = u.y; al[mt][2] = u.z; al[mt][3] = u.w;
            }
#pragma unroll
            for (int nt = 0; nt < 4; ++nt) {
                uint2 t = *(const uint2*)&Bs_hi[BIDX(ks, wn * 4 + nt, lane, 0)];
                bh[nt][0] = t.x; bh[nt][1] = t.y;
                uint2 u = *(const uint2*)&Bs_lo[BIDX(ks, wn * 4 + nt, lane, 0)];
                bl[nt][0] = u.x; bl[nt][1] = u.y;
            }
#pragma unroll
            for (int mt = 0; mt < 4; ++mt)
#pragma unroll
                for (int nt = 0; nt < 4; ++nt) {
                    mma_tf32(acc[mt][nt], ah[mt], bl[nt]);
                    mma_tf32(acc[mt][nt], al[mt], bh[nt]);
                    mma_tf32(acc[mt][nt], ah[mt], bh[nt]);
                }
        }
        __syncthreads();
    }

    // ---- epilogue ----
    int gi_ = lane >> 2, ti = lane & 3;
#pragma unroll
    for (int mt = 0; mt < 4; ++mt) {
#pragma unroll
        for (int nt = 0; nt < 4; ++nt) {
            int row = m0 + wm * 64 + mt * 16 + gi_;
            int col = n0 + wn * 32 + nt * 8 + 2 * ti;
            if (col >= N) continue;
            float b0 = bias[col], b1 = bias[col + 1];
            if (row < M) {
                float2 v = make_float2(acc[mt][nt][0] + b0, acc[mt][nt][1] + b1);
                *(float2*)&C[(size_t)row * ldc + col] = v;
            }
            if (row + 8 < M) {
                float2 v = make_float2(acc[mt][nt][2] + b0, acc[mt][nt][3] + b1);
                *(float2*)&C[(size_t)(row + 8) * ldc + col] = v;
            }
        }
    }
}

// ---------------- CSR gather-aggregate ----------------
__global__ void aggregate(const float* __restrict__ m, const float* __restrict__ biasinc,
                          const int* __restrict__ rowptr, const int* __restrict__ ebase,
                          float* __restrict__ inc) {
    int node = blockIdx.x;
    int i = threadIdx.x;
    if (i >= D) return;
    int s = rowptr[node], e = rowptr[node + 1];
    float acc = biasinc[(size_t)node * D + i];
    for (int p = s; p < e; ++p)
        acc += m[(size_t)ebase[p] + i];
    inc[(size_t)node * KLD + i] = acc;
}

// ---------------- GRU elementwise ----------------
__global__ void gru_kernel(const float* __restrict__ gi, const float* __restrict__ o1,
                           float* __restrict__ h, int n_nodes) {
    int idx = blockIdx.x * blockDim.x + threadIdx.x;
    if (idx >= n_nodes * D) return;
    int node = idx / D, i = idx - node * D;
    const float* gir = gi + (size_t)node * GILD;
    const float* ghr = o1 + (size_t)node * MLD + 600;
    float ir = gir[i], iz = gir[D + i], inn = gir[2 * D + i];
    float hr = ghr[i], hz = ghr[D + i], hn = ghr[2 * D + i];
    float r = 1.f / (1.f + expf(-(ir + hr)));
    float z = 1.f / (1.f + expf(-(iz + hz)));
    float nn = tanhf(inn + r * hn);
    size_t hidx = (size_t)node * KLD + i;
    h[hidx] = (1.f - z) * nn + z * h[hidx];
}

// ---------------- readout + MLP ----------------
__global__ void gstart_init(int* __restrict__ gstart, int n_nodes) {
    int g = threadIdx.x;
    if (g <= NG) gstart[g] = (g == NG) ? n_nodes : 0x7fffffff;
}
__global__ void gstart_min(const int* __restrict__ gids, int* __restrict__ gstart, int n) {
    int i = blockIdx.x * blockDim.x + threadIdx.x;
    if (i < n) atomicMin(&gstart[gids[i]], i);
}
__global__ void gstart_fix(int* __restrict__ gstart) {
    if (threadIdx.x == 0)
        for (int g = NG - 1; g >= 0; --g)
            if (gstart[g] == 0x7fffffff) gstart[g] = gstart[g + 1];
}

__global__ void readout(const float* __restrict__ h, const int* __restrict__ gstart,
                        const float* __restrict__ pclass, float* __restrict__ x) {
    int g = blockIdx.x;
    int i = threadIdx.x;
    int s = gstart[g], e = gstart[g + 1];
    if (i < D) {
        float acc = 0.f;
        for (int n = s; n < e; ++n) acc += h[(size_t)n * KLD + i];
        float l = logf(acc);
        if (l != l) l = 0.f;
        l = fmaxf(l, 0.f);
        x[g * XLD + i] = l;
    }
    if (i == D) x[g * XLD + D] = pclass[g];
}

__global__ void mlp_kernel(const float* __restrict__ x,
                           const float* __restrict__ fc1w, const float* __restrict__ fc1b,
                           const float* __restrict__ fc2w, const float* __restrict__ fc2b,
                           float* __restrict__ out) {
    __shared__ float xb[D + 1];
    __shared__ float hid[HIDN];
    int g = blockIdx.x, t = threadIdx.x;
    if (t < D + 1) xb[t] = x[g * XLD + t];
    __syncthreads();
    float acc = fc1b[t];
    for (int k = 0; k < D + 1; ++k) acc += xb[k] * fc1w[k * HIDN + t];
    hid[t] = acc > 0.f ? acc : 0.01f * acc;
    __syncthreads();
    if (t < 10) {
        float o = fc2b[t];
        for (int k = 0; k < HIDN; ++k) o += hid[k] * fc2w[k * 10 + t];
        out[g * 10 + t] = o;
    }
}

// ---------------- launch ----------------
extern "C" void kernel_launch(void* const* d_in, const int* in_sizes, int n_in,
                              void* d_out, int out_size) {
    const float* nodes  = (const float*)d_in[0];
    const float* pclass = (const float*)d_in[1];
    const int*   esrc   = (const int*)d_in[2];
    const int*   edst   = (const int*)d_in[3];
    const int*   etype  = (const int*)d_in[4];
    const int*   gids   = (const int*)d_in[5];
    const float* We     = (const float*)d_in[6];
    const float* be     = (const float*)d_in[7];
    const float* wih    = (const float*)d_in[8];
    const float* whh    = (const float*)d_in[9];
    const float* bih    = (const float*)d_in[10];
    const float* bhh    = (const float*)d_in[11];
    const float* fc1w   = (const float*)d_in[12];
    const float* fc1b   = (const float*)d_in[13];
    const float* fc2w   = (const float*)d_in[14];
    const float* fc2b   = (const float*)d_in[15];
    float* out = (float*)d_out;

    int n_nodes = in_sizes[0] / D;
    int E = in_sizes[2];

    float *h_p, *inc_p, *o1_p, *gi_p, *bi_p, *wbig_p, *wih_p, *b1_p, *x_p;
    int *degt_p, *rowptr_p, *cursor_p, *ebase_p, *gstart_p;
    cudaGetSymbolAddress((void**)&h_p, g_h);
    cudaGetSymbolAddress((void**)&inc_p, g_inc);
    cudaGetSymbolAddress((void**)&o1_p, g_out1);
    cudaGetSymbolAddress((void**)&gi_p, g_gi);
    cudaGetSymbolAddress((void**)&bi_p, g_biasinc);
    cudaGetSymbolAddress((void**)&wbig_p, g_Wbig);
    cudaGetSymbolAddress((void**)&wih_p, g_wih);
    cudaGetSymbolAddress((void**)&b1_p, g_bias1);
    cudaGetSymbolAddress((void**)&x_p, g_x);
    cudaGetSymbolAddress((void**)&degt_p, g_degt);
    cudaGetSymbolAddress((void**)&rowptr_p, g_rowptr);
    cudaGetSymbolAddress((void**)&cursor_p, g_cursor);
    cudaGetSymbolAddress((void**)&ebase_p, g_ebase);
    cudaGetSymbolAddress((void**)&gstart_p, g_gstart);

    static int smem_set = 0;
    if (!smem_set) {
        cudaFuncSetAttribute(gemm_3xtf32, cudaFuncAttributeMaxDynamicSharedMemorySize,
                             (2 * SM_A + 2 * SM_B) * 4);
        smem_set = 1;
    }

    // setup (kernel-launch indices 0..4; GEMM1 of pass 0 lands at index 5 for ncu -s 5)
    int setup_items = NN * NT + NC1 * KLD + 450 * KLD + NC1;
    setup_weights<<<(setup_items + 255) / 256, 256>>>(We, whh, wih, bhh,
                                                      wbig_p, wih_p, b1_p, degt_p);
    int copy_items = NN * KLD + NN * (KLD - D);
    copy_h<<<(copy_items + 255) / 256, 256>>>(nodes, h_p, inc_p);
    hist_kernel<<<(E + 255) / 256, 256>>>(edst, etype, degt_p, E);
    scan_kernel<<<1, 1024>>>(degt_p, rowptr_p, cursor_p, n_nodes);
    biasinc_kernel<<<(n_nodes * D + 255) / 256, 256>>>(degt_p, be, bi_p, n_nodes);

    dim3 g1((NC1 + 127) / 128, (n_nodes + 127) / 128);
    dim3 g2((450 + 127) / 128, (n_nodes + 127) / 128);
    size_t smem_bytes = (2 * SM_A + 2 * SM_B) * 4;

    for (int p = 0; p < PASSES; ++p) {
        gemm_3xtf32<<<g1, 256, smem_bytes>>>(h_p, wbig_p, o1_p, MLD, n_nodes, NC1, b1_p);
        if (p == 0)
            csr_fill<<<(E + 255) / 256, 256>>>(esrc, edst, etype, cursor_p, ebase_p, E);
        aggregate<<<n_nodes, 160>>>(o1_p, bi_p, rowptr_p, ebase_p, inc_p);
        gemm_3xtf32<<<g2, 256, smem_bytes>>>(inc_p, wih_p, gi_p, GILD, n_nodes, 450, bih);
        gru_kernel<<<(n_nodes * D + 255) / 256, 256>>>(gi_p, o1_p, h_p, n_nodes);
    }

    gstart_init<<<1, NG + 1>>>(gstart_p, n_nodes);
    gstart_min<<<(n_nodes + 255) / 256, 256>>>(gids, gstart_p, n_nodes);
    gstart_fix<<<1, 1>>>(gstart_p);
    readout<<<NG, 160>>>(h_p, gstart_p, pclass, x_p);
    mlp_kernel<<<NG, HIDN>>>(x_p, fc1w, fc1b, fc2w, fc2b, out);
}

// round 6
// speedup vs baseline: 1.4832x; 1.4832x over previous
#include <cuda_runtime.h>
#include <cuda_fp16.h>
#include <math.h>
#include <stdint.h>

#define NN 100000
#define NE 800000
#define NG 64
#define NT 4
#define D 150
#define HIDN 512
#define PASSES 5
#define NC1 1050
#define MLD 1056
#define GILD 456
#define XLD 152
#define KLD 160
#define BLW 80        // packed half2 words per B row (160 halves)
#define B1ROWS 1152
#define B2ROWS 512

__device__ float g_h[(size_t)NN * KLD];
__device__ float g_inc[(size_t)NN * KLD];
__device__ float g_out1[(size_t)NN * MLD];
__device__ float g_gi[(size_t)NN * GILD];
__device__ float g_biasinc[(size_t)NN * D];
__device__ uint32_t g_B1h[B1ROWS * BLW];
__device__ uint32_t g_B1m[B1ROWS * BLW];
__device__ uint32_t g_B2h[B2ROWS * BLW];
__device__ uint32_t g_B2m[B2ROWS * BLW];
__device__ float g_bias1[NC1];
__device__ int   g_degt[NN * NT];
__device__ int   g_rowptr[NN + 1];
__device__ int   g_cursor[NN];
__device__ int   g_ebase[NE];
__device__ int   g_gstart[NG + 1];
__device__ float g_x[NG * XLD];

// pack two floats into half2 word (x0 -> low, x1 -> high)
__device__ __forceinline__ uint32_t packh(float x0, float x1) {
    __half2 h = __floats2half2_rn(x0, x1);
    return *reinterpret_cast<uint32_t*>(&h);
}
// split pair: returns hi word, writes mid word
__device__ __forceinline__ uint32_t split2(float x0, float x1, uint32_t* mid) {
    __half h0 = __float2half_rn(x0), h1 = __float2half_rn(x1);
    float m0 = x0 - __half2float(h0), m1 = x1 - __half2float(h1);
    *mid = packh(m0, m1);
    __half2 hh = __halves2half2(h0, h1);
    return *reinterpret_cast<uint32_t*>(&hh);
}

__device__ __forceinline__ void mma_f16(float* d, const uint32_t* a, const uint32_t* b) {
    asm volatile(
        "mma.sync.aligned.m16n8k16.row.col.f32.f16.f16.f32 "
        "{%0,%1,%2,%3}, {%4,%5,%6,%7}, {%8,%9}, {%0,%1,%2,%3};"
        : "+f"(d[0]), "+f"(d[1]), "+f"(d[2]), "+f"(d[3])
        : "r"(a[0]), "r"(a[1]), "r"(a[2]), "r"(a[3]), "r"(b[0]), "r"(b[1]));
}

// ---------- setup: zero degt, split-pack weights, bias1 ----------
__global__ void setup_weights(const float* __restrict__ We, const float* __restrict__ whh,
                              const float* __restrict__ wih, const float* __restrict__ bhh,
                              uint32_t* __restrict__ B1h, uint32_t* __restrict__ B1m,
                              uint32_t* __restrict__ B2h, uint32_t* __restrict__ B2m,
                              float* __restrict__ bias1, int* __restrict__ degt) {
    int idx = blockIdx.x * blockDim.x + threadIdx.x;
    if (idx < NN * NT) { degt[idx] = 0; return; }
    idx -= NN * NT;
    if (idx < (B1ROWS + B2ROWS) * BLW) {
        int two = (idx >= B1ROWS * BLW);
        int li = two ? idx - B1ROWS * BLW : idx;
        int n = li / BLW, w = li - n * BLW;
        int c0 = 2 * w, c1 = c0 + 1;
        float w0 = 0.f, w1 = 0.f;
        if (!two) {
            if (n < 600) {
                if (c0 < D) w0 = We[n * D + c0];
                if (c1 < D) w1 = We[n * D + c1];
            } else if (n < NC1) {
                if (c0 < D) w0 = whh[(n - 600) * D + c0];
                if (c1 < D) w1 = whh[(n - 600) * D + c1];
            }
        } else if (n < 450) {
            if (c0 < D) w0 = wih[n * D + c0];
            if (c1 < D) w1 = wih[n * D + c1];
        }
        uint32_t mid;
        uint32_t hi = split2(w0, w1, &mid);
        if (!two) { B1h[li] = hi; B1m[li] = mid; }
        else      { B2h[li] = hi; B2m[li] = mid; }
        return;
    }
    idx -= (B1ROWS + B2ROWS) * BLW;
    if (idx < NC1) bias1[idx] = (idx < 600) ? 0.f : bhh[idx - 600];
}

__global__ void copy_h(const float* __restrict__ nodes, float* __restrict__ h,
                       float* __restrict__ inc) {
    int idx = blockIdx.x * blockDim.x + threadIdx.x;
    if (idx < NN * KLD) {
        int node = idx / KLD, c = idx - node * KLD;
        h[idx] = (c < D) ? nodes[node * D + c] : 0.f;
        return;
    }
    idx -= NN * KLD;
    if (idx < NN * (KLD - D)) {
        int node = idx / (KLD - D), c = D + idx % (KLD - D);
        inc[node * KLD + c] = 0.f;
    }
}

__global__ void hist_kernel(const int* __restrict__ dst, const int* __restrict__ etype,
                            int* __restrict__ degt, int E) {
    int e = blockIdx.x * blockDim.x + threadIdx.x;
    if (e < E) atomicAdd(&degt[dst[e] * NT + etype[e]], 1);
}

__global__ void biasinc_kernel(const int* __restrict__ degt, const float* __restrict__ be,
                               float* __restrict__ biasinc, int n_nodes) {
    int idx = blockIdx.x * blockDim.x + threadIdx.x;
    if (idx >= n_nodes * D) return;
    int node = idx / D, i = idx - node * D;
    float s = 0.f;
#pragma unroll
    for (int t = 0; t < NT; ++t) s += (float)degt[node * NT + t] * be[t * D + i];
    biasinc[idx] = s;
}

__global__ void scan_kernel(const int* __restrict__ degt, int* __restrict__ rowptr,
                            int* __restrict__ cursor, int n) {
    __shared__ int warp_tot[32];
    __shared__ int carry_s;
    int tid = threadIdx.x, lane = tid & 31, wid = tid >> 5;
    if (tid == 0) carry_s = 0;
    __syncthreads();
    for (int base = 0; base < n; base += 1024) {
        int idx = base + tid;
        int v = 0;
        if (idx < n)
            v = degt[idx * NT] + degt[idx * NT + 1] + degt[idx * NT + 2] + degt[idx * NT + 3];
        int x = v;
#pragma unroll
        for (int off = 1; off < 32; off <<= 1) {
            int y = __shfl_up_sync(0xffffffffu, x, off);
            if (lane >= off) x += y;
        }
        if (lane == 31) warp_tot[wid] = x;
        __syncthreads();
        if (wid == 0) {
            int w = warp_tot[lane], wx = w;
#pragma unroll
            for (int off = 1; off < 32; off <<= 1) {
                int y = __shfl_up_sync(0xffffffffu, wx, off);
                if (lane >= off) wx += y;
            }
            warp_tot[lane] = wx - w;
        }
        __syncthreads();
        int excl = carry_s + warp_tot[wid] + x - v;
        if (idx < n) { rowptr[idx] = excl; cursor[idx] = excl; }
        __syncthreads();
        if (tid == 1023) carry_s = excl + v;
        __syncthreads();
    }
    if (tid == 0) rowptr[n] = carry_s;
}

__global__ void csr_fill(const int* __restrict__ src, const int* __restrict__ dst,
                         const int* __restrict__ etype, int* __restrict__ cursor,
                         int* __restrict__ ebase, int E) {
    int e = blockIdx.x * blockDim.x + threadIdx.x;
    if (e >= E) return;
    int pos = atomicAdd(&cursor[dst[e]], 1);
    ebase[pos] = src[e] * MLD + etype[e] * D;
}

// ---------- fp16 3-split GEMM via m16n8k16: C = A@B^T + bias ----------
// A fp32 [M, KLD]; B pre-split packed half2 [rows, BLW]. K = 160 (10 k16 steps).
// smem fragment arrays (u32/half2 units):
//   As/Am: [ks10][mt8][lane32][reg4]  (10240 each)
//   Bs/Bm: [ks10][nt16][lane32][reg2] (10240 each)
#define AOFF(ks, mt, ln, rg) ((((ks) * 8 + (mt)) * 32 + (ln)) * 4 + (rg))
#define BOFF(ks, nt, ln, rg) ((((ks) * 16 + (nt)) * 32 + (ln)) * 2 + (rg))
#define SEG 10240
#define GEMM_SMEM (4 * SEG * 4)

__global__ __launch_bounds__(256) void gemm_f16(
    const float* __restrict__ A,
    const uint32_t* __restrict__ Bh, const uint32_t* __restrict__ Bm,
    float* __restrict__ C, int ldc, int M, int N,
    const float* __restrict__ bias) {
    extern __shared__ uint32_t sm[];
    uint32_t* As = sm;
    uint32_t* Am = sm + SEG;
    uint32_t* Bs = sm + 2 * SEG;
    uint32_t* Bm_ = sm + 3 * SEG;

    int tid = threadIdx.x;
    int lane = tid & 31, wid = tid >> 5;
    int wm = wid & 1, wn = wid >> 1;
    int m0 = blockIdx.y * 128, n0 = blockIdx.x * 128;

    float acc[4][4][4];
#pragma unroll
    for (int i = 0; i < 4; ++i)
#pragma unroll
        for (int j = 0; j < 4; ++j)
#pragma unroll
            for (int r = 0; r < 4; ++r) acc[i][j][r] = 0.f;

    int ra = tid >> 1, qa = tid & 1;
    // ---- stage A (split into hi/mid fragments) ----
    {
        int gm = m0 + ra;
        int mt = ra >> 4, rloc = ra & 15;
        int rhalf = rloc >> 3, lbase = (rloc & 7) * 4;
        const float* arow = A + (size_t)gm * KLD;
#pragma unroll
        for (int q = 0; q < 10; ++q) {
            int kbase = qa * 80 + q * 8;
            float4 v1 = make_float4(0.f, 0.f, 0.f, 0.f), v2 = v1;
            if (gm < M) {
                v1 = *(const float4*)(arow + kbase);
                v2 = *(const float4*)(arow + kbase + 4);
            }
            int ks = kbase >> 4;
            int reg = rhalf + 2 * ((kbase >> 3) & 1);
            uint32_t mw;
            uint32_t hw = split2(v1.x, v1.y, &mw);
            As[AOFF(ks, mt, lbase + 0, reg)] = hw; Am[AOFF(ks, mt, lbase + 0, reg)] = mw;
            hw = split2(v1.z, v1.w, &mw);
            As[AOFF(ks, mt, lbase + 1, reg)] = hw; Am[AOFF(ks, mt, lbase + 1, reg)] = mw;
            hw = split2(v2.x, v2.y, &mw);
            As[AOFF(ks, mt, lbase + 2, reg)] = hw; Am[AOFF(ks, mt, lbase + 2, reg)] = mw;
            hw = split2(v2.z, v2.w, &mw);
            As[AOFF(ks, mt, lbase + 3, reg)] = hw; Am[AOFF(ks, mt, lbase + 3, reg)] = mw;
        }
    }
    // ---- stage B (pre-split; rows padded so no guard) ----
    {
        int nt = ra >> 3, lbase = (ra & 7) * 4;
        size_t rowb = (size_t)(n0 + ra) * BLW;
#pragma unroll
        for (int q = 0; q < 10; ++q) {
            int wbase = qa * 40 + q * 4;
            uint4 vh = *(const uint4*)(Bh + rowb + wbase);
            uint4 vm = *(const uint4*)(Bm + rowb + wbase);
            int ks = wbase >> 3;
            int reg = (wbase >> 2) & 1;
            Bs[BOFF(ks, nt, lbase + 0, reg)] = vh.x; Bm_[BOFF(ks, nt, lbase + 0, reg)] = vm.x;
            Bs[BOFF(ks, nt, lbase + 1, reg)] = vh.y; Bm_[BOFF(ks, nt, lbase + 1, reg)] = vm.y;
            Bs[BOFF(ks, nt, lbase + 2, reg)] = vh.z; Bm_[BOFF(ks, nt, lbase + 2, reg)] = vm.z;
            Bs[BOFF(ks, nt, lbase + 3, reg)] = vh.w; Bm_[BOFF(ks, nt, lbase + 3, reg)] = vm.w;
        }
    }
    __syncthreads();

    // ---- compute: per ks, per 16 tiles, 3 MMAs (hh + h*mid + mid*h) ----
#pragma unroll
    for (int ks = 0; ks < 10; ++ks) {
        uint32_t ah[4][4], am[4][4], bh[4][2], bm[4][2];
#pragma unroll
        for (int mt = 0; mt < 4; ++mt) {
            uint4 t = *(const uint4*)&As[AOFF(ks, wm * 4 + mt, lane, 0)];
            ah[mt][0] = t.x; ah[mt][1] = t.y; ah[mt][2] = t.z; ah[mt][3] = t.w;
            uint4 u = *(const uint4*)&Am[AOFF(ks, wm * 4 + mt, lane, 0)];
            am[mt][0] = u.x; am[mt][1] = u.y; am[mt][2] = u.z; am[mt][3] = u.w;
        }
#pragma unroll
        for (int nt = 0; nt < 4; ++nt) {
            uint2 t = *(const uint2*)&Bs[BOFF(ks, wn * 4 + nt, lane, 0)];
            bh[nt][0] = t.x; bh[nt][1] = t.y;
            uint2 u = *(const uint2*)&Bm_[BOFF(ks, wn * 4 + nt, lane, 0)];
            bm[nt][0] = u.x; bm[nt][1] = u.y;
        }
#pragma unroll
        for (int mt = 0; mt < 4; ++mt)
#pragma unroll
            for (int nt = 0; nt < 4; ++nt) {
                mma_f16(acc[mt][nt], ah[mt], bm[nt]);
                mma_f16(acc[mt][nt], am[mt], bh[nt]);
                mma_f16(acc[mt][nt], ah[mt], bh[nt]);
            }
    }

    // ---- epilogue ----
    int gi_ = lane >> 2, ti = lane & 3;
#pragma unroll
    for (int mt = 0; mt < 4; ++mt) {
#pragma unroll
        for (int nt = 0; nt < 4; ++nt) {
            int row = m0 + wm * 64 + mt * 16 + gi_;
            int col = n0 + wn * 32 + nt * 8 + 2 * ti;
            if (col >= N) continue;
            float b0 = bias[col], b1 = bias[col + 1];
            if (row < M) {
                float2 v = make_float2(acc[mt][nt][0] + b0, acc[mt][nt][1] + b1);
                *(float2*)&C[(size_t)row * ldc + col] = v;
            }
            if (row + 8 < M) {
                float2 v = make_float2(acc[mt][nt][2] + b0, acc[mt][nt][3] + b1);
                *(float2*)&C[(size_t)(row + 8) * ldc + col] = v;
            }
        }
    }
}

// ---------- CSR gather-aggregate ----------
__global__ void aggregate(const float* __restrict__ m, const float* __restrict__ biasinc,
                          const int* __restrict__ rowptr, const int* __restrict__ ebase,
                          float* __restrict__ inc) {
    int node = blockIdx.x;
    int i = threadIdx.x;
    if (i >= D) return;
    int s = rowptr[node], e = rowptr[node + 1];
    float acc = biasinc[(size_t)node * D + i];
    for (int p = s; p < e; ++p) acc += m[(size_t)ebase[p] + i];
    inc[(size_t)node * KLD + i] = acc;
}

// ---------- GRU elementwise ----------
__global__ void gru_kernel(const float* __restrict__ gi, const float* __restrict__ o1,
                           float* __restrict__ h, int n_nodes) {
    int idx = blockIdx.x * blockDim.x + threadIdx.x;
    if (idx >= n_nodes * D) return;
    int node = idx / D, i = idx - node * D;
    const float* gir = gi + (size_t)node * GILD;
    const float* ghr = o1 + (size_t)node * MLD + 600;
    float ir = gir[i], iz = gir[D + i], inn = gir[2 * D + i];
    float hr = ghr[i], hz = ghr[D + i], hn = ghr[2 * D + i];
    float r = 1.f / (1.f + expf(-(ir + hr)));
    float z = 1.f / (1.f + expf(-(iz + hz)));
    float nn = tanhf(inn + r * hn);
    size_t hidx = (size_t)node * KLD + i;
    h[hidx] = (1.f - z) * nn + z * h[hidx];
}

// ---------- readout + MLP ----------
__global__ void gstart_init(int* __restrict__ gstart, int n_nodes) {
    int g = threadIdx.x;
    if (g <= NG) gstart[g] = (g == NG) ? n_nodes : 0x7fffffff;
}
__global__ void gstart_min(const int* __restrict__ gids, int* __restrict__ gstart, int n) {
    int i = blockIdx.x * blockDim.x + threadIdx.x;
    if (i < n) atomicMin(&gstart[gids[i]], i);
}
__global__ void gstart_fix(int* __restrict__ gstart) {
    if (threadIdx.x == 0)
        for (int g = NG - 1; g >= 0; --g)
            if (gstart[g] == 0x7fffffff) gstart[g] = gstart[g + 1];
}
__global__ void readout(const float* __restrict__ h, const int* __restrict__ gstart,
                        const float* __restrict__ pclass, float* __restrict__ x) {
    int g = blockIdx.x, i = threadIdx.x;
    int s = gstart[g], e = gstart[g + 1];
    if (i < D) {
        float acc = 0.f;
        for (int n = s; n < e; ++n) acc += h[(size_t)n * KLD + i];
        float l = logf(acc);
        if (l != l) l = 0.f;
        l = fmaxf(l, 0.f);
        x[g * XLD + i] = l;
    }
    if (i == D) x[g * XLD + D] = pclass[g];
}
__global__ void mlp_kernel(const float* __restrict__ x,
                           const float* __restrict__ fc1w, const float* __restrict__ fc1b,
                           const float* __restrict__ fc2w, const float* __restrict__ fc2b,
                           float* __restrict__ out) {
    __shared__ float xb[D + 1];
    __shared__ float hid[HIDN];
    int g = blockIdx.x, t = threadIdx.x;
    if (t < D + 1) xb[t] = x[g * XLD + t];
    __syncthreads();
    float acc = fc1b[t];
    for (int k = 0; k < D + 1; ++k) acc += xb[k] * fc1w[k * HIDN + t];
    hid[t] = acc > 0.f ? acc : 0.01f * acc;
    __syncthreads();
    if (t < 10) {
        float o = fc2b[t];
        for (int k = 0; k < HIDN; ++k) o += hid[k] * fc2w[k * 10 + t];
        out[g * 10 + t] = o;
    }
}

// ---------- launch ----------
extern "C" void kernel_launch(void* const* d_in, const int* in_sizes, int n_in,
                              void* d_out, int out_size) {
    const float* nodes  = (const float*)d_in[0];
    const float* pclass = (const float*)d_in[1];
    const int*   esrc   = (const int*)d_in[2];
    const int*   edst   = (const int*)d_in[3];
    const int*   etype  = (const int*)d_in[4];
    const int*   gids   = (const int*)d_in[5];
    const float* We     = (const float*)d_in[6];
    const float* be     = (const float*)d_in[7];
    const float* wih    = (const float*)d_in[8];
    const float* whh    = (const float*)d_in[9];
    const float* bih    = (const float*)d_in[10];
    const float* bhh    = (const float*)d_in[11];
    const float* fc1w   = (const float*)d_in[12];
    const float* fc1b   = (const float*)d_in[13];
    const float* fc2w   = (const float*)d_in[14];
    const float* fc2b   = (const float*)d_in[15];
    float* out = (float*)d_out;

    int n_nodes = in_sizes[0] / D;
    int E = in_sizes[2];

    float *h_p, *inc_p, *o1_p, *gi_p, *bi_p, *b1_p, *x_p;
    uint32_t *b1h_p, *b1m_p, *b2h_p, *b2m_p;
    int *degt_p, *rowptr_p, *cursor_p, *ebase_p, *gstart_p;
    cudaGetSymbolAddress((void**)&h_p, g_h);
    cudaGetSymbolAddress((void**)&inc_p, g_inc);
    cudaGetSymbolAddress((void**)&o1_p, g_out1);
    cudaGetSymbolAddress((void**)&gi_p, g_gi);
    cudaGetSymbolAddress((void**)&bi_p, g_biasinc);
    cudaGetSymbolAddress((void**)&b1h_p, g_B1h);
    cudaGetSymbolAddress((void**)&b1m_p, g_B1m);
    cudaGetSymbolAddress((void**)&b2h_p, g_B2h);
    cudaGetSymbolAddress((void**)&b2m_p, g_B2m);
    cudaGetSymbolAddress((void**)&b1_p, g_bias1);
    cudaGetSymbolAddress((void**)&x_p, g_x);
    cudaGetSymbolAddress((void**)&degt_p, g_degt);
    cudaGetSymbolAddress((void**)&rowptr_p, g_rowptr);
    cudaGetSymbolAddress((void**)&cursor_p, g_cursor);
    cudaGetSymbolAddress((void**)&ebase_p, g_ebase);
    cudaGetSymbolAddress((void**)&gstart_p, g_gstart);

    cudaFuncSetAttribute(gemm_f16, cudaFuncAttributeMaxDynamicSharedMemorySize, GEMM_SMEM);

    int setup_items = NN * NT + (B1ROWS + B2ROWS) * BLW + NC1;
    setup_weights<<<(setup_items + 255) / 256, 256>>>(We, whh, wih, bhh,
        b1h_p, b1m_p, b2h_p, b2m_p, b1_p, degt_p);
    int copy_items = NN * KLD + NN * (KLD - D);
    copy_h<<<(copy_items + 255) / 256, 256>>>(nodes, h_p, inc_p);
    hist_kernel<<<(E + 255) / 256, 256>>>(edst, etype, degt_p, E);

    dim3 g1(9, (n_nodes + 127) / 128);
    dim3 g2(4, (n_nodes + 127) / 128);

    for (int p = 0; p < PASSES; ++p) {
        gemm_f16<<<g1, 256, GEMM_SMEM>>>(h_p, b1h_p, b1m_p, o1_p, MLD, n_nodes, NC1, b1_p);
        if (p == 0) {
            scan_kernel<<<1, 1024>>>(degt_p, rowptr_p, cursor_p, n_nodes);
            biasinc_kernel<<<(n_nodes * D + 255) / 256, 256>>>(degt_p, be, bi_p, n_nodes);
            csr_fill<<<(E + 255) / 256, 256>>>(esrc, edst, etype, cursor_p, ebase_p, E);
        }
        aggregate<<<n_nodes, 160>>>(o1_p, bi_p, rowptr_p, ebase_p, inc_p);
        gemm_f16<<<g2, 256, GEMM_SMEM>>>(inc_p, b2h_p, b2m_p, gi_p, GILD, n_nodes, 450, bih);
        gru_kernel<<<(n_nodes * D + 255) / 256, 256>>>(gi_p, o1_p, h_p, n_nodes);
    }

    gstart_init<<<1, NG + 1>>>(gstart_p, n_nodes);
    gstart_min<<<(n_nodes + 255) / 256, 256>>>(gids, gstart_p, n_nodes);
    gstart_fix<<<1, 1>>>(gstart_p);
    readout<<<NG, 160>>>(h_p, gstart_p, pclass, x_p);
    mlp_kernel<<<NG, HIDN>>>(x_p, fc1w, fc1b, fc2w, fc2b, out);
}

// round 7
// speedup vs baseline: 1.9457x; 1.3118x over previous
#include <cuda_runtime.h>
#include <cuda_fp16.h>
#include <math.h>
#include <stdint.h>

#define NN 100000
#define NE 800000
#define NG 64
#define NT 4
#define D 150
#define HIDN 512
#define PASSES 5
#define NC1 1050
#define MLD 1056
#define GILD 456
#define XLD 152
#define KLD 160
#define BLW 80        // packed half2 words per B row (160 halves)
#define B1ROWS 1152
#define B2ROWS 512

__device__ float g_h[(size_t)NN * KLD];
__device__ float g_inc[(size_t)NN * KLD];
__device__ float g_out1[(size_t)NN * MLD];
__device__ float g_gi[(size_t)NN * GILD];
__device__ float g_biasinc[(size_t)NN * D];
__device__ uint32_t g_B1h[B1ROWS * BLW];
__device__ uint32_t g_B1m[B1ROWS * BLW];
__device__ uint32_t g_B2h[B2ROWS * BLW];
__device__ uint32_t g_B2m[B2ROWS * BLW];
__device__ float g_bias1[NC1];
__device__ int   g_degt[NN * NT];
__device__ int   g_rowptr[NN + 1];
__device__ int   g_cursor[NN];
__device__ int   g_ebase[NE];
__device__ int   g_gstart[NG + 1];
__device__ float g_x[NG * XLD];

__device__ __forceinline__ uint32_t packh(float x0, float x1) {
    __half2 h = __floats2half2_rn(x0, x1);
    return *reinterpret_cast<uint32_t*>(&h);
}
__device__ __forceinline__ uint32_t split2(float x0, float x1, uint32_t* mid) {
    __half h0 = __float2half_rn(x0), h1 = __float2half_rn(x1);
    float m0 = x0 - __half2float(h0), m1 = x1 - __half2float(h1);
    *mid = packh(m0, m1);
    __half2 hh = __halves2half2(h0, h1);
    return *reinterpret_cast<uint32_t*>(&hh);
}

__device__ __forceinline__ void mma_f16(float* d, const uint32_t* a, const uint32_t* b) {
    asm volatile(
        "mma.sync.aligned.m16n8k16.row.col.f32.f16.f16.f32 "
        "{%0,%1,%2,%3}, {%4,%5,%6,%7}, {%8,%9}, {%0,%1,%2,%3};"
        : "+f"(d[0]), "+f"(d[1]), "+f"(d[2]), "+f"(d[3])
        : "r"(a[0]), "r"(a[1]), "r"(a[2]), "r"(a[3]), "r"(b[0]), "r"(b[1]));
}

// ---------- setup ----------
__global__ void setup_weights(const float* __restrict__ We, const float* __restrict__ whh,
                              const float* __restrict__ wih, const float* __restrict__ bhh,
                              uint32_t* __restrict__ B1h, uint32_t* __restrict__ B1m,
                              uint32_t* __restrict__ B2h, uint32_t* __restrict__ B2m,
                              float* __restrict__ bias1, int* __restrict__ degt) {
    int idx = blockIdx.x * blockDim.x + threadIdx.x;
    if (idx < NN * NT) { degt[idx] = 0; return; }
    idx -= NN * NT;
    if (idx < (B1ROWS + B2ROWS) * BLW) {
        int two = (idx >= B1ROWS * BLW);
        int li = two ? idx - B1ROWS * BLW : idx;
        int n = li / BLW, w = li - n * BLW;
        int c0 = 2 * w, c1 = c0 + 1;
        float w0 = 0.f, w1 = 0.f;
        if (!two) {
            if (n < 600) {
                if (c0 < D) w0 = We[n * D + c0];
                if (c1 < D) w1 = We[n * D + c1];
            } else if (n < NC1) {
                if (c0 < D) w0 = whh[(n - 600) * D + c0];
                if (c1 < D) w1 = whh[(n - 600) * D + c1];
            }
        } else if (n < 450) {
            if (c0 < D) w0 = wih[n * D + c0];
            if (c1 < D) w1 = wih[n * D + c1];
        }
        uint32_t mid;
        uint32_t hi = split2(w0, w1, &mid);
        if (!two) { B1h[li] = hi; B1m[li] = mid; }
        else      { B2h[li] = hi; B2m[li] = mid; }
        return;
    }
    idx -= (B1ROWS + B2ROWS) * BLW;
    if (idx < NC1) bias1[idx] = (idx < 600) ? 0.f : bhh[idx - 600];
}

__global__ void copy_h(const float* __restrict__ nodes, float* __restrict__ h,
                       float* __restrict__ inc) {
    int idx = blockIdx.x * blockDim.x + threadIdx.x;
    if (idx < NN * KLD) {
        int node = idx / KLD, c = idx - node * KLD;
        h[idx] = (c < D) ? nodes[node * D + c] : 0.f;
        return;
    }
    idx -= NN * KLD;
    if (idx < NN * (KLD - D)) {
        int node = idx / (KLD - D), c = D + idx % (KLD - D);
        inc[node * KLD + c] = 0.f;
    }
}

__global__ void hist_kernel(const int* __restrict__ dst, const int* __restrict__ etype,
                            int* __restrict__ degt, int E) {
    int e = blockIdx.x * blockDim.x + threadIdx.x;
    if (e < E) atomicAdd(&degt[dst[e] * NT + etype[e]], 1);
}

__global__ void biasinc_kernel(const int* __restrict__ degt, const float* __restrict__ be,
                               float* __restrict__ biasinc, int n_nodes) {
    int idx = blockIdx.x * blockDim.x + threadIdx.x;
    if (idx >= n_nodes * D) return;
    int node = idx / D, i = idx - node * D;
    float s = 0.f;
#pragma unroll
    for (int t = 0; t < NT; ++t) s += (float)degt[node * NT + t] * be[t * D + i];
    biasinc[idx] = s;
}

__global__ void scan_kernel(const int* __restrict__ degt, int* __restrict__ rowptr,
                            int* __restrict__ cursor, int n) {
    __shared__ int warp_tot[32];
    __shared__ int carry_s;
    int tid = threadIdx.x, lane = tid & 31, wid = tid >> 5;
    if (tid == 0) carry_s = 0;
    __syncthreads();
    for (int base = 0; base < n; base += 1024) {
        int idx = base + tid;
        int v = 0;
        if (idx < n)
            v = degt[idx * NT] + degt[idx * NT + 1] + degt[idx * NT + 2] + degt[idx * NT + 3];
        int x = v;
#pragma unroll
        for (int off = 1; off < 32; off <<= 1) {
            int y = __shfl_up_sync(0xffffffffu, x, off);
            if (lane >= off) x += y;
        }
        if (lane == 31) warp_tot[wid] = x;
        __syncthreads();
        if (wid == 0) {
            int w = warp_tot[lane], wx = w;
#pragma unroll
            for (int off = 1; off < 32; off <<= 1) {
                int y = __shfl_up_sync(0xffffffffu, wx, off);
                if (lane >= off) wx += y;
            }
            warp_tot[lane] = wx - w;
        }
        __syncthreads();
        int excl = carry_s + warp_tot[wid] + x - v;
        if (idx < n) { rowptr[idx] = excl; cursor[idx] = excl; }
        __syncthreads();
        if (tid == 1023) carry_s = excl + v;
        __syncthreads();
    }
    if (tid == 0) rowptr[n] = carry_s;
}

__global__ void csr_fill(const int* __restrict__ src, const int* __restrict__ dst,
                         const int* __restrict__ etype, int* __restrict__ cursor,
                         int* __restrict__ ebase, int E) {
    int e = blockIdx.x * blockDim.x + threadIdx.x;
    if (e >= E) return;
    int pos = atomicAdd(&cursor[dst[e]], 1);
    ebase[pos] = src[e] * MLD + etype[e] * D;
}

// ---------- fp16 3-split GEMM, 2 K-chunks (80KB smem -> 2 CTAs/SM) ----------
// chunk = 5 k16 steps (80 fp32 cols). smem u32 arrays per chunk window:
//   As/Am: [ks5][mt8][lane32][reg4] = 5120 ; Bs/Bm: [ks5][nt16][lane32][reg2] = 5120
#define AOFF(ks, mt, ln, rg) ((((ks) * 8 + (mt)) * 32 + (ln)) * 4 + (rg))
#define BOFF(ks, nt, ln, rg) ((((ks) * 16 + (nt)) * 32 + (ln)) * 2 + (rg))
#define SEG 5120
#define GEMM_SMEM (4 * SEG * 4)

__global__ __launch_bounds__(256, 2) void gemm_f16(
    const float* __restrict__ A,
    const uint32_t* __restrict__ Bh, const uint32_t* __restrict__ Bm,
    float* __restrict__ C, int ldc, int M, int N,
    const float* __restrict__ bias) {
    extern __shared__ uint32_t sm[];
    uint32_t* As = sm;
    uint32_t* Am = sm + SEG;
    uint32_t* Bs = sm + 2 * SEG;
    uint32_t* Bm_ = sm + 3 * SEG;

    int tid = threadIdx.x;
    int lane = tid & 31, wid = tid >> 5;
    int wm = wid & 1, wn = wid >> 1;
    int m0 = blockIdx.y * 128, n0 = blockIdx.x * 128;

    float acc[4][4][4];
#pragma unroll
    for (int i = 0; i < 4; ++i)
#pragma unroll
        for (int j = 0; j < 4; ++j)
#pragma unroll
            for (int r = 0; r < 4; ++r) acc[i][j][r] = 0.f;

    int ra = tid >> 1, qa = tid & 1;
    int gm = m0 + ra;
    int a_mt = ra >> 4, a_rloc = ra & 15;
    int a_rhalf = a_rloc >> 3, a_lbase = (a_rloc & 7) * 4;
    int b_nt = ra >> 3, b_lbase = (ra & 7) * 4;
    const float* arow = A + (size_t)gm * KLD;
    size_t rowb = (size_t)(n0 + ra) * BLW;

#pragma unroll
    for (int c = 0; c < 2; ++c) {
        if (c) __syncthreads();  // protect smem reuse
        // ---- stage A chunk (split) ----
#pragma unroll
        for (int q = 0; q < 5; ++q) {
            int kloc = qa * 40 + q * 8;           // 0..72 within chunk
            int kg = c * 80 + kloc;               // global col
            float4 v1 = make_float4(0.f, 0.f, 0.f, 0.f), v2 = v1;
            if (gm < M) {
                v1 = *(const float4*)(arow + kg);
                v2 = *(const float4*)(arow + kg + 4);
            }
            int ks = kloc >> 4;
            int reg = a_rhalf + 2 * ((kloc >> 3) & 1);
            uint32_t mw;
            uint32_t hw = split2(v1.x, v1.y, &mw);
            As[AOFF(ks, a_mt, a_lbase + 0, reg)] = hw; Am[AOFF(ks, a_mt, a_lbase + 0, reg)] = mw;
            hw = split2(v1.z, v1.w, &mw);
            As[AOFF(ks, a_mt, a_lbase + 1, reg)] = hw; Am[AOFF(ks, a_mt, a_lbase + 1, reg)] = mw;
            hw = split2(v2.x, v2.y, &mw);
            As[AOFF(ks, a_mt, a_lbase + 2, reg)] = hw; Am[AOFF(ks, a_mt, a_lbase + 2, reg)] = mw;
            hw = split2(v2.z, v2.w, &mw);
            As[AOFF(ks, a_mt, a_lbase + 3, reg)] = hw; Am[AOFF(ks, a_mt, a_lbase + 3, reg)] = mw;
        }
        // ---- stage B chunk (pre-split; rows padded) ----
#pragma unroll
        for (int q = 0; q < 5; ++q) {
            int wloc = qa * 20 + q * 4;           // half2 words within chunk
            uint4 vh = *(const uint4*)(Bh + rowb + c * 40 + wloc);
            uint4 vm = *(const uint4*)(Bm + rowb + c * 40 + wloc);
            int ks = wloc >> 3;
            int reg = (wloc >> 2) & 1;
            Bs[BOFF(ks, b_nt, b_lbase + 0, reg)] = vh.x; Bm_[BOFF(ks, b_nt, b_lbase + 0, reg)] = vm.x;
            Bs[BOFF(ks, b_nt, b_lbase + 1, reg)] = vh.y; Bm_[BOFF(ks, b_nt, b_lbase + 1, reg)] = vm.y;
            Bs[BOFF(ks, b_nt, b_lbase + 2, reg)] = vh.z; Bm_[BOFF(ks, b_nt, b_lbase + 2, reg)] = vm.z;
            Bs[BOFF(ks, b_nt, b_lbase + 3, reg)] = vh.w; Bm_[BOFF(ks, b_nt, b_lbase + 3, reg)] = vm.w;
        }
        __syncthreads();
        // ---- compute chunk ----
#pragma unroll
        for (int ks = 0; ks < 5; ++ks) {
            uint32_t ah[4][4], am[4][4], bh[4][2], bm[4][2];
#pragma unroll
            for (int mt = 0; mt < 4; ++mt) {
                uint4 t = *(const uint4*)&As[AOFF(ks, wm * 4 + mt, lane, 0)];
                ah[mt][0] = t.x; ah[mt][1] = t.y; ah[mt][2] = t.z; ah[mt][3] = t.w;
                uint4 u = *(const uint4*)&Am[AOFF(ks, wm * 4 + mt, lane, 0)];
                am[mt][0] = u.x; am[mt][1] = u.y; am[mt][2] = u.z; am[mt][3] = u.w;
            }
#pragma unroll
            for (int nt = 0; nt < 4; ++nt) {
                uint2 t = *(const uint2*)&Bs[BOFF(ks, wn * 4 + nt, lane, 0)];
                bh[nt][0] = t.x; bh[nt][1] = t.y;
                uint2 u = *(const uint2*)&Bm_[BOFF(ks, wn * 4 + nt, lane, 0)];
                bm[nt][0] = u.x; bm[nt][1] = u.y;
            }
#pragma unroll
            for (int mt = 0; mt < 4; ++mt)
#pragma unroll
                for (int nt = 0; nt < 4; ++nt) {
                    mma_f16(acc[mt][nt], ah[mt], bm[nt]);
                    mma_f16(acc[mt][nt], am[mt], bh[nt]);
                    mma_f16(acc[mt][nt], ah[mt], bh[nt]);
                }
        }
    }

    // ---- epilogue ----
    int gi_ = lane >> 2, ti = lane & 3;
#pragma unroll
    for (int mt = 0; mt < 4; ++mt) {
#pragma unroll
        for (int nt = 0; nt < 4; ++nt) {
            int row = m0 + wm * 64 + mt * 16 + gi_;
            int col = n0 + wn * 32 + nt * 8 + 2 * ti;
            if (col >= N) continue;
            float b0 = bias[col], b1 = bias[col + 1];
            if (row < M) {
                float2 v = make_float2(acc[mt][nt][0] + b0, acc[mt][nt][1] + b1);
                *(float2*)&C[(size_t)row * ldc + col] = v;
            }
            if (row + 8 < M) {
                float2 v = make_float2(acc[mt][nt][2] + b0, acc[mt][nt][3] + b1);
                *(float2*)&C[(size_t)(row + 8) * ldc + col] = v;
            }
        }
    }
}

// ---------- CSR gather-aggregate ----------
__global__ void aggregate(const float* __restrict__ m, const float* __restrict__ biasinc,
                          const int* __restrict__ rowptr, const int* __restrict__ ebase,
                          float* __restrict__ inc) {
    int node = blockIdx.x;
    int i = threadIdx.x;
    if (i >= D) return;
    int s = rowptr[node], e = rowptr[node + 1];
    float acc = biasinc[(size_t)node * D + i];
    for (int p = s; p < e; ++p) acc += m[(size_t)ebase[p] + i];
    inc[(size_t)node * KLD + i] = acc;
}

// ---------- GRU elementwise ----------
__global__ void gru_kernel(const float* __restrict__ gi, const float* __restrict__ o1,
                           float* __restrict__ h, int n_nodes) {
    int idx = blockIdx.x * blockDim.x + threadIdx.x;
    if (idx >= n_nodes * D) return;
    int node = idx / D, i = idx - node * D;
    const float* gir = gi + (size_t)node * GILD;
    const float* ghr = o1 + (size_t)node * MLD + 600;
    float ir = gir[i], iz = gir[D + i], inn = gir[2 * D + i];
    float hr = ghr[i], hz = ghr[D + i], hn = ghr[2 * D + i];
    float r = 1.f / (1.f + expf(-(ir + hr)));
    float z = 1.f / (1.f + expf(-(iz + hz)));
    float nn = tanhf(inn + r * hn);
    size_t hidx = (size_t)node * KLD + i;
    h[hidx] = (1.f - z) * nn + z * h[hidx];
}

// ---------- readout + MLP ----------
__global__ void gstart_init(int* __restrict__ gstart, int n_nodes) {
    int g = threadIdx.x;
    if (g <= NG) gstart[g] = (g == NG) ? n_nodes : 0x7fffffff;
}
__global__ void gstart_min(const int* __restrict__ gids, int* __restrict__ gstart, int n) {
    int i = blockIdx.x * blockDim.x + threadIdx.x;
    if (i < n) atomicMin(&gstart[gids[i]], i);
}
__global__ void gstart_fix(int* __restrict__ gstart) {
    if (threadIdx.x == 0)
        for (int g = NG - 1; g >= 0; --g)
            if (gstart[g] == 0x7fffffff) gstart[g] = gstart[g + 1];
}
__global__ void readout(const float* __restrict__ h, const int* __restrict__ gstart,
                        const float* __restrict__ pclass, float* __restrict__ x) {
    int g = blockIdx.x, i = threadIdx.x;
    int s = gstart[g], e = gstart[g + 1];
    if (i < D) {
        float acc = 0.f;
        for (int n = s; n < e; ++n) acc += h[(size_t)n * KLD + i];
        float l = logf(acc);
        if (l != l) l = 0.f;
        l = fmaxf(l, 0.f);
        x[g * XLD + i] = l;
    }
    if (i == D) x[g * XLD + D] = pclass[g];
}
__global__ void mlp_kernel(const float* __restrict__ x,
                           const float* __restrict__ fc1w, const float* __restrict__ fc1b,
                           const float* __restrict__ fc2w, const float* __restrict__ fc2b,
                           float* __restrict__ out) {
    __shared__ float xb[D + 1];
    __shared__ float hid[HIDN];
    int g = blockIdx.x, t = threadIdx.x;
    if (t < D + 1) xb[t] = x[g * XLD + t];
    __syncthreads();
    float acc = fc1b[t];
    for (int k = 0; k < D + 1; ++k) acc += xb[k] * fc1w[k * HIDN + t];
    hid[t] = acc > 0.f ? acc : 0.01f * acc;
    __syncthreads();
    if (t < 10) {
        float o = fc2b[t];
        for (int k = 0; k < HIDN; ++k) o += hid[k] * fc2w[k * 10 + t];
        out[g * 10 + t] = o;
    }
}

// ---------- launch ----------
extern "C" void kernel_launch(void* const* d_in, const int* in_sizes, int n_in,
                              void* d_out, int out_size) {
    const float* nodes  = (const float*)d_in[0];
    const float* pclass = (const float*)d_in[1];
    const int*   esrc   = (const int*)d_in[2];
    const int*   edst   = (const int*)d_in[3];
    const int*   etype  = (const int*)d_in[4];
    const int*   gids   = (const int*)d_in[5];
    const float* We     = (const float*)d_in[6];
    const float* be     = (const float*)d_in[7];
    const float* wih    = (const float*)d_in[8];
    const float* whh    = (const float*)d_in[9];
    const float* bih    = (const float*)d_in[10];
    const float* bhh    = (const float*)d_in[11];
    const float* fc1w   = (const float*)d_in[12];
    const float* fc1b   = (const float*)d_in[13];
    const float* fc2w   = (const float*)d_in[14];
    const float* fc2b   = (const float*)d_in[15];
    float* out = (float*)d_out;

    int n_nodes = in_sizes[0] / D;
    int E = in_sizes[2];

    float *h_p, *inc_p, *o1_p, *gi_p, *bi_p, *b1_p, *x_p;
    uint32_t *b1h_p, *b1m_p, *b2h_p, *b2m_p;
    int *degt_p, *rowptr_p, *cursor_p, *ebase_p, *gstart_p;
    cudaGetSymbolAddress((void**)&h_p, g_h);
    cudaGetSymbolAddress((void**)&inc_p, g_inc);
    cudaGetSymbolAddress((void**)&o1_p, g_out1);
    cudaGetSymbolAddress((void**)&gi_p, g_gi);
    cudaGetSymbolAddress((void**)&bi_p, g_biasinc);
    cudaGetSymbolAddress((void**)&b1h_p, g_B1h);
    cudaGetSymbolAddress((void**)&b1m_p, g_B1m);
    cudaGetSymbolAddress((void**)&b2h_p, g_B2h);
    cudaGetSymbolAddress((void**)&b2m_p, g_B2m);
    cudaGetSymbolAddress((void**)&b1_p, g_bias1);
    cudaGetSymbolAddress((void**)&x_p, g_x);
    cudaGetSymbolAddress((void**)&degt_p, g_degt);
    cudaGetSymbolAddress((void**)&rowptr_p, g_rowptr);
    cudaGetSymbolAddress((void**)&cursor_p, g_cursor);
    cudaGetSymbolAddress((void**)&ebase_p, g_ebase);
    cudaGetSymbolAddress((void**)&gstart_p, g_gstart);

    cudaFuncSetAttribute(gemm_f16, cudaFuncAttributeMaxDynamicSharedMemorySize, GEMM_SMEM);

    int setup_items = NN * NT + (B1ROWS + B2ROWS) * BLW + NC1;
    setup_weights<<<(setup_items + 255) / 256, 256>>>(We, whh, wih, bhh,
        b1h_p, b1m_p, b2h_p, b2m_p, b1_p, degt_p);
    int copy_items = NN * KLD + NN * (KLD - D);
    copy_h<<<(copy_items + 255) / 256, 256>>>(nodes, h_p, inc_p);
    hist_kernel<<<(E + 255) / 256, 256>>>(edst, etype, degt_p, E);

    dim3 g1(9, (n_nodes + 127) / 128);
    dim3 g2(4, (n_nodes + 127) / 128);

    for (int p = 0; p < PASSES; ++p) {
        gemm_f16<<<g1, 256, GEMM_SMEM>>>(h_p, b1h_p, b1m_p, o1_p, MLD, n_nodes, NC1, b1_p);
        if (p == 0) {
            scan_kernel<<<1, 1024>>>(degt_p, rowptr_p, cursor_p, n_nodes);
            biasinc_kernel<<<(n_nodes * D + 255) / 256, 256>>>(degt_p, be, bi_p, n_nodes);
            csr_fill<<<(E + 255) / 256, 256>>>(esrc, edst, etype, cursor_p, ebase_p, E);
        }
        aggregate<<<n_nodes, 160>>>(o1_p, bi_p, rowptr_p, ebase_p, inc_p);
        gemm_f16<<<g2, 256, GEMM_SMEM>>>(inc_p, b2h_p, b2m_p, gi_p, GILD, n_nodes, 450, bih);
        gru_kernel<<<(n_nodes * D + 255) / 256, 256>>>(gi_p, o1_p, h_p, n_nodes);
    }

    gstart_init<<<1, NG + 1>>>(gstart_p, n_nodes);
    gstart_min<<<(n_nodes + 255) / 256, 256>>>(gids, gstart_p, n_nodes);
    gstart_fix<<<1, 1>>>(gstart_p);
    readout<<<NG, 160>>>(h_p, gstart_p, pclass, x_p);
    mlp_kernel<<<NG, HIDN>>>(x_p, fc1w, fc1b, fc2w, fc2b, out);
}

// round 8
// speedup vs baseline: 2.1786x; 1.1197x over previous
#include <cuda_runtime.h>
#include <cuda_fp16.h>
#include <math.h>
#include <stdint.h>

#define NN 100000
#define NE 800000
#define NG 64
#define NT 4
#define D 150
#define HIDN 512
#define PASSES 5
#define NC1 1050
#define MLD 1056
#define GILD 456
#define XLD 152
#define KLD 160
#define NB1 9          // GEMM1 column blocks
#define NB2 4          // GEMM2 column blocks
#define FBLK (10 * 16 * 32 * 2)   // u32 per column block of fragments

__device__ float g_h[(size_t)NN * KLD];
__device__ float g_inc[(size_t)NN * KLD];
__device__ float g_out1[(size_t)NN * MLD];
__device__ float g_gi[(size_t)NN * GILD];
__device__ float g_biasinc[(size_t)NN * D];
__device__ uint32_t g_F1h[NB1 * FBLK];
__device__ uint32_t g_F1m[NB1 * FBLK];
__device__ uint32_t g_F2h[NB2 * FBLK];
__device__ uint32_t g_F2m[NB2 * FBLK];
__device__ float g_bias1[NC1];
__device__ int   g_degt[NN * NT];
__device__ int   g_rowptr[NN + 1];
__device__ int   g_cursor[NN];
__device__ int   g_ebase[NE];
__device__ int   g_gstart[NG + 1];
__device__ float g_x[NG * XLD];

__device__ __forceinline__ uint32_t packh(float x0, float x1) {
    __half2 h = __floats2half2_rn(x0, x1);
    return *reinterpret_cast<uint32_t*>(&h);
}
__device__ __forceinline__ uint32_t split2(float x0, float x1, uint32_t* mid) {
    __half h0 = __float2half_rn(x0), h1 = __float2half_rn(x1);
    float m0 = x0 - __half2float(h0), m1 = x1 - __half2float(h1);
    *mid = packh(m0, m1);
    __half2 hh = __halves2half2(h0, h1);
    return *reinterpret_cast<uint32_t*>(&hh);
}
__device__ __forceinline__ void mma_f16(float* d, const uint32_t* a, const uint32_t* b) {
    asm volatile(
        "mma.sync.aligned.m16n8k16.row.col.f32.f16.f16.f32 "
        "{%0,%1,%2,%3}, {%4,%5,%6,%7}, {%8,%9}, {%0,%1,%2,%3};"
        : "+f"(d[0]), "+f"(d[1]), "+f"(d[2]), "+f"(d[3])
        : "r"(a[0]), "r"(a[1]), "r"(a[2]), "r"(a[3]), "r"(b[0]), "r"(b[1]));
}

// ---------- setup: zero degt, build fragment-ordered split weights, bias1 ---
// Fragment (blk, ks, nt, lane, reg) holds half2 of W[n, 2w], W[n, 2w+1]
// with n = blk*128 + nt*8 + (lane>>2),  w = ks*8 + reg*4 + (lane&3).
__global__ void setup_weights(const float* __restrict__ We, const float* __restrict__ whh,
                              const float* __restrict__ wih, const float* __restrict__ bhh,
                              uint32_t* __restrict__ F1h, uint32_t* __restrict__ F1m,
                              uint32_t* __restrict__ F2h, uint32_t* __restrict__ F2m,
                              float* __restrict__ bias1, int* __restrict__ degt) {
    int idx = blockIdx.x * blockDim.x + threadIdx.x;
    if (idx < NN * NT) { degt[idx] = 0; return; }
    idx -= NN * NT;
    if (idx < (NB1 + NB2) * FBLK) {
        int two = (idx >= NB1 * FBLK);
        int li = two ? idx - NB1 * FBLK : idx;
        int blk = li / FBLK, r = li % FBLK;
        int ks = r >> 10, r2 = r & 1023;
        int nt = r2 >> 6, r3 = r2 & 63;
        int lane = r3 >> 1, reg = r3 & 1;
        int n = blk * 128 + nt * 8 + (lane >> 2);
        int w = ks * 8 + reg * 4 + (lane & 3);
        int c0 = 2 * w, c1 = c0 + 1;
        float w0 = 0.f, w1 = 0.f;
        if (!two) {
            if (n < 600) {
                if (c0 < D) w0 = We[n * D + c0];
                if (c1 < D) w1 = We[n * D + c1];
            } else if (n < NC1) {
                if (c0 < D) w0 = whh[(n - 600) * D + c0];
                if (c1 < D) w1 = whh[(n - 600) * D + c1];
            }
        } else if (n < 450) {
            if (c0 < D) w0 = wih[n * D + c0];
            if (c1 < D) w1 = wih[n * D + c1];
        }
        uint32_t mid;
        uint32_t hi = split2(w0, w1, &mid);
        if (!two) { F1h[li] = hi; F1m[li] = mid; }
        else      { F2h[li] = hi; F2m[li] = mid; }
        return;
    }
    idx -= (NB1 + NB2) * FBLK;
    if (idx < NC1) bias1[idx] = (idx < 600) ? 0.f : bhh[idx - 600];
}

__global__ void copy_h(const float* __restrict__ nodes, float* __restrict__ h,
                       float* __restrict__ inc) {
    int idx = blockIdx.x * blockDim.x + threadIdx.x;
    if (idx < NN * KLD) {
        int node = idx / KLD, c = idx - node * KLD;
        h[idx] = (c < D) ? nodes[node * D + c] : 0.f;
        return;
    }
    idx -= NN * KLD;
    if (idx < NN * (KLD - D)) {
        int node = idx / (KLD - D), c = D + idx % (KLD - D);
        inc[node * KLD + c] = 0.f;
    }
}

__global__ void hist_kernel(const int* __restrict__ dst, const int* __restrict__ etype,
                            int* __restrict__ degt, int E) {
    int e = blockIdx.x * blockDim.x + threadIdx.x;
    if (e < E) atomicAdd(&degt[dst[e] * NT + etype[e]], 1);
}

__global__ void biasinc_kernel(const int* __restrict__ degt, const float* __restrict__ be,
                               float* __restrict__ biasinc, int n_nodes) {
    int idx = blockIdx.x * blockDim.x + threadIdx.x;
    if (idx >= n_nodes * D) return;
    int node = idx / D, i = idx - node * D;
    float s = 0.f;
#pragma unroll
    for (int t = 0; t < NT; ++t) s += (float)degt[node * NT + t] * be[t * D + i];
    biasinc[idx] = s;
}

__global__ void scan_kernel(const int* __restrict__ degt, int* __restrict__ rowptr,
                            int* __restrict__ cursor, int n) {
    __shared__ int warp_tot[32];
    __shared__ int carry_s;
    int tid = threadIdx.x, lane = tid & 31, wid = tid >> 5;
    if (tid == 0) carry_s = 0;
    __syncthreads();
    for (int base = 0; base < n; base += 1024) {
        int idx = base + tid;
        int v = 0;
        if (idx < n)
            v = degt[idx * NT] + degt[idx * NT + 1] + degt[idx * NT + 2] + degt[idx * NT + 3];
        int x = v;
#pragma unroll
        for (int off = 1; off < 32; off <<= 1) {
            int y = __shfl_up_sync(0xffffffffu, x, off);
            if (lane >= off) x += y;
        }
        if (lane == 31) warp_tot[wid] = x;
        __syncthreads();
        if (wid == 0) {
            int w = warp_tot[lane], wx = w;
#pragma unroll
            for (int off = 1; off < 32; off <<= 1) {
                int y = __shfl_up_sync(0xffffffffu, wx, off);
                if (lane >= off) wx += y;
            }
            warp_tot[lane] = wx - w;
        }
        __syncthreads();
        int excl = carry_s + warp_tot[wid] + x - v;
        if (idx < n) { rowptr[idx] = excl; cursor[idx] = excl; }
        __syncthreads();
        if (tid == 1023) carry_s = excl + v;
        __syncthreads();
    }
    if (tid == 0) rowptr[n] = carry_s;
}

__global__ void csr_fill(const int* __restrict__ src, const int* __restrict__ dst,
                         const int* __restrict__ etype, int* __restrict__ cursor,
                         int* __restrict__ ebase, int E) {
    int e = blockIdx.x * blockDim.x + threadIdx.x;
    if (e >= E) return;
    int pos = atomicAdd(&cursor[dst[e]], 1);
    ebase[pos] = src[e] * MLD + etype[e] * D;
}

// ---------- fp16 3-split GEMM: A staged in smem (full K), B fragments from gmem
// A smem: As/Am [ks10][mt8][lane32][reg4] = 10240 u32 each -> 80KB total
#define AOFF(ks, mt, ln, rg) ((((ks) * 8 + (mt)) * 32 + (ln)) * 4 + (rg))
#define SEG 10240
#define GEMM_SMEM (2 * SEG * 4)

__global__ __launch_bounds__(256, 2) void gemm_f16(
    const float* __restrict__ A,
    const uint32_t* __restrict__ Fh, const uint32_t* __restrict__ Fm,
    float* __restrict__ C, int ldc, int M, int N,
    const float* __restrict__ bias) {
    extern __shared__ uint32_t sm[];
    uint32_t* As = sm;
    uint32_t* Am = sm + SEG;

    int tid = threadIdx.x;
    int lane = tid & 31, wid = tid >> 5;
    int wm = wid & 1, wn = wid >> 1;
    int m0 = blockIdx.y * 128, n0 = blockIdx.x * 128;

    float acc[4][4][4];
#pragma unroll
    for (int i = 0; i < 4; ++i)
#pragma unroll
        for (int j = 0; j < 4; ++j)
#pragma unroll
            for (int r = 0; r < 4; ++r) acc[i][j][r] = 0.f;

    int ra = tid >> 1, qa = tid & 1;
    // ---- stage A full K (split into hi/mid fragments) ----
    {
        int gm = m0 + ra;
        int mt = ra >> 4, rloc = ra & 15;
        int rhalf = rloc >> 3, lbase = (rloc & 7) * 4;
        const float* arow = A + (size_t)gm * KLD;
#pragma unroll
        for (int q = 0; q < 10; ++q) {
            int kbase = qa * 80 + q * 8;
            float4 v1 = make_float4(0.f, 0.f, 0.f, 0.f), v2 = v1;
            if (gm < M) {
                v1 = *(const float4*)(arow + kbase);
                v2 = *(const float4*)(arow + kbase + 4);
            }
            int ks = kbase >> 4;
            int reg = rhalf + 2 * ((kbase >> 3) & 1);
            uint32_t mw;
            uint32_t hw = split2(v1.x, v1.y, &mw);
            As[AOFF(ks, mt, lbase + 0, reg)] = hw; Am[AOFF(ks, mt, lbase + 0, reg)] = mw;
            hw = split2(v1.z, v1.w, &mw);
            As[AOFF(ks, mt, lbase + 1, reg)] = hw; Am[AOFF(ks, mt, lbase + 1, reg)] = mw;
            hw = split2(v2.x, v2.y, &mw);
            As[AOFF(ks, mt, lbase + 2, reg)] = hw; Am[AOFF(ks, mt, lbase + 2, reg)] = mw;
            hw = split2(v2.z, v2.w, &mw);
            As[AOFF(ks, mt, lbase + 3, reg)] = hw; Am[AOFF(ks, mt, lbase + 3, reg)] = mw;
        }
    }
    __syncthreads();

    // B fragment base for this column block (fragment-ordered in gmem, L2-hot)
    const uint32_t* fbh = Fh + (size_t)blockIdx.x * FBLK;
    const uint32_t* fbm = Fm + (size_t)blockIdx.x * FBLK;

#pragma unroll
    for (int ks = 0; ks < 10; ++ks) {
        uint32_t ah[4][4], am[4][4], bh[4][2], bm[4][2];
#pragma unroll
        for (int mt = 0; mt < 4; ++mt) {
            uint4 t = *(const uint4*)&As[AOFF(ks, wm * 4 + mt, lane, 0)];
            ah[mt][0] = t.x; ah[mt][1] = t.y; ah[mt][2] = t.z; ah[mt][3] = t.w;
            uint4 u = *(const uint4*)&Am[AOFF(ks, wm * 4 + mt, lane, 0)];
            am[mt][0] = u.x; am[mt][1] = u.y; am[mt][2] = u.z; am[mt][3] = u.w;
        }
#pragma unroll
        for (int nt = 0; nt < 4; ++nt) {
            size_t o = (((size_t)ks * 16 + wn * 4 + nt) * 32 + lane) * 2;
            uint2 t = __ldg((const uint2*)(fbh + o));
            bh[nt][0] = t.x; bh[nt][1] = t.y;
            uint2 u = __ldg((const uint2*)(fbm + o));
            bm[nt][0] = u.x; bm[nt][1] = u.y;
        }
#pragma unroll
        for (int mt = 0; mt < 4; ++mt)
#pragma unroll
            for (int nt = 0; nt < 4; ++nt) {
                mma_f16(acc[mt][nt], ah[mt], bm[nt]);
                mma_f16(acc[mt][nt], am[mt], bh[nt]);
                mma_f16(acc[mt][nt], ah[mt], bh[nt]);
            }
    }

    // ---- epilogue ----
    int gi_ = lane >> 2, ti = lane & 3;
#pragma unroll
    for (int mt = 0; mt < 4; ++mt) {
#pragma unroll
        for (int nt = 0; nt < 4; ++nt) {
            int row = m0 + wm * 64 + mt * 16 + gi_;
            int col = n0 + wn * 32 + nt * 8 + 2 * ti;
            if (col >= N) continue;
            float b0 = bias[col], b1 = bias[col + 1];
            if (row < M) {
                float2 v = make_float2(acc[mt][nt][0] + b0, acc[mt][nt][1] + b1);
                *(float2*)&C[(size_t)row * ldc + col] = v;
            }
            if (row + 8 < M) {
                float2 v = make_float2(acc[mt][nt][2] + b0, acc[mt][nt][3] + b1);
                *(float2*)&C[(size_t)(row + 8) * ldc + col] = v;
            }
        }
    }
}

// ---------- CSR gather-aggregate (MLP-4 unrolled) ----------
__global__ void aggregate(const float* __restrict__ m, const float* __restrict__ biasinc,
                          const int* __restrict__ rowptr, const int* __restrict__ ebase,
                          float* __restrict__ inc) {
    int node = blockIdx.x;
    int i = threadIdx.x;
    if (i >= D) return;
    int s = rowptr[node], e = rowptr[node + 1];
    float acc = biasinc[(size_t)node * D + i];
    int p = s;
    for (; p + 3 < e; p += 4) {
        int b0 = ebase[p], b1 = ebase[p + 1], b2 = ebase[p + 2], b3 = ebase[p + 3];
        float v0 = m[(size_t)b0 + i];
        float v1 = m[(size_t)b1 + i];
        float v2 = m[(size_t)b2 + i];
        float v3 = m[(size_t)b3 + i];
        acc += (v0 + v1) + (v2 + v3);
    }
    for (; p < e; ++p) acc += m[(size_t)ebase[p] + i];
    inc[(size_t)node * KLD + i] = acc;
}

// ---------- GRU elementwise ----------
__global__ void gru_kernel(const float* __restrict__ gi, const float* __restrict__ o1,
                           float* __restrict__ h, int n_nodes) {
    int idx = blockIdx.x * blockDim.x + threadIdx.x;
    if (idx >= n_nodes * D) return;
    int node = idx / D, i = idx - node * D;
    const float* gir = gi + (size_t)node * GILD;
    const float* ghr = o1 + (size_t)node * MLD + 600;
    float ir = gir[i], iz = gir[D + i], inn = gir[2 * D + i];
    float hr = ghr[i], hz = ghr[D + i], hn = ghr[2 * D + i];
    float r = 1.f / (1.f + expf(-(ir + hr)));
    float z = 1.f / (1.f + expf(-(iz + hz)));
    float nn = tanhf(inn + r * hn);
    size_t hidx = (size_t)node * KLD + i;
    h[hidx] = (1.f - z) * nn + z * h[hidx];
}

// ---------- readout + MLP ----------
__global__ void gstart_init(int* __restrict__ gstart, int n_nodes) {
    int g = threadIdx.x;
    if (g <= NG) gstart[g] = (g == NG) ? n_nodes : 0x7fffffff;
}
__global__ void gstart_min(const int* __restrict__ gids, int* __restrict__ gstart, int n) {
    int i = blockIdx.x * blockDim.x + threadIdx.x;
    if (i < n) atomicMin(&gstart[gids[i]], i);
}
__global__ void gstart_fix(int* __restrict__ gstart) {
    if (threadIdx.x == 0)
        for (int g = NG - 1; g >= 0; --g)
            if (gstart[g] == 0x7fffffff) gstart[g] = gstart[g + 1];
}
__global__ void readout(const float* __restrict__ h, const int* __restrict__ gstart,
                        const float* __restrict__ pclass, float* __restrict__ x) {
    int g = blockIdx.x, i = threadIdx.x;
    int s = gstart[g], e = gstart[g + 1];
    if (i < D) {
        float acc = 0.f;
        for (int n = s; n < e; ++n) acc += h[(size_t)n * KLD + i];
        float l = logf(acc);
        if (l != l) l = 0.f;
        l = fmaxf(l, 0.f);
        x[g * XLD + i] = l;
    }
    if (i == D) x[g * XLD + D] = pclass[g];
}
__global__ void mlp_kernel(const float* __restrict__ x,
                           const float* __restrict__ fc1w, const float* __restrict__ fc1b,
                           const float* __restrict__ fc2w, const float* __restrict__ fc2b,
                           float* __restrict__ out) {
    __shared__ float xb[D + 1];
    __shared__ float hid[HIDN];
    int g = blockIdx.x, t = threadIdx.x;
    if (t < D + 1) xb[t] = x[g * XLD + t];
    __syncthreads();
    float acc = fc1b[t];
    for (int k = 0; k < D + 1; ++k) acc += xb[k] * fc1w[k * HIDN + t];
    hid[t] = acc > 0.f ? acc : 0.01f * acc;
    __syncthreads();
    if (t < 10) {
        float o = fc2b[t];
        for (int k = 0; k < HIDN; ++k) o += hid[k] * fc2w[k * 10 + t];
        out[g * 10 + t] = o;
    }
}

// ---------- launch ----------
extern "C" void kernel_launch(void* const* d_in, const int* in_sizes, int n_in,
                              void* d_out, int out_size) {
    const float* nodes  = (const float*)d_in[0];
    const float* pclass = (const float*)d_in[1];
    const int*   esrc   = (const int*)d_in[2];
    const int*   edst   = (const int*)d_in[3];
    const int*   etype  = (const int*)d_in[4];
    const int*   gids   = (const int*)d_in[5];
    const float* We     = (const float*)d_in[6];
    const float* be     = (const float*)d_in[7];
    const float* wih    = (const float*)d_in[8];
    const float* whh    = (const float*)d_in[9];
    const float* bih    = (const float*)d_in[10];
    const float* bhh    = (const float*)d_in[11];
    const float* fc1w   = (const float*)d_in[12];
    const float* fc1b   = (const float*)d_in[13];
    const float* fc2w   = (const float*)d_in[14];
    const float* fc2b   = (const float*)d_in[15];
    float* out = (float*)d_out;

    int n_nodes = in_sizes[0] / D;
    int E = in_sizes[2];

    float *h_p, *inc_p, *o1_p, *gi_p, *bi_p, *b1_p, *x_p;
    uint32_t *f1h_p, *f1m_p, *f2h_p, *f2m_p;
    int *degt_p, *rowptr_p, *cursor_p, *ebase_p, *gstart_p;
    cudaGetSymbolAddress((void**)&h_p, g_h);
    cudaGetSymbolAddress((void**)&inc_p, g_inc);
    cudaGetSymbolAddress((void**)&o1_p, g_out1);
    cudaGetSymbolAddress((void**)&gi_p, g_gi);
    cudaGetSymbolAddress((void**)&bi_p, g_biasinc);
    cudaGetSymbolAddress((void**)&f1h_p, g_F1h);
    cudaGetSymbolAddress((void**)&f1m_p, g_F1m);
    cudaGetSymbolAddress((void**)&f2h_p, g_F2h);
    cudaGetSymbolAddress((void**)&f2m_p, g_F2m);
    cudaGetSymbolAddress((void**)&b1_p, g_bias1);
    cudaGetSymbolAddress((void**)&x_p, g_x);
    cudaGetSymbolAddress((void**)&degt_p, g_degt);
    cudaGetSymbolAddress((void**)&rowptr_p, g_rowptr);
    cudaGetSymbolAddress((void**)&cursor_p, g_cursor);
    cudaGetSymbolAddress((void**)&ebase_p, g_ebase);
    cudaGetSymbolAddress((void**)&gstart_p, g_gstart);

    cudaFuncSetAttribute(gemm_f16, cudaFuncAttributeMaxDynamicSharedMemorySize, GEMM_SMEM);

    int setup_items = NN * NT + (NB1 + NB2) * FBLK + NC1;
    setup_weights<<<(setup_items + 255) / 256, 256>>>(We, whh, wih, bhh,
        f1h_p, f1m_p, f2h_p, f2m_p, b1_p, degt_p);
    int copy_items = NN * KLD + NN * (KLD - D);
    copy_h<<<(copy_items + 255) / 256, 256>>>(nodes, h_p, inc_p);
    hist_kernel<<<(E + 255) / 256, 256>>>(edst, etype, degt_p, E);

    dim3 g1(NB1, (n_nodes + 127) / 128);
    dim3 g2(NB2, (n_nodes + 127) / 128);

    for (int p = 0; p < PASSES; ++p) {
        gemm_f16<<<g1, 256, GEMM_SMEM>>>(h_p, f1h_p, f1m_p, o1_p, MLD, n_nodes, NC1, b1_p);
        if (p == 0) {
            scan_kernel<<<1, 1024>>>(degt_p, rowptr_p, cursor_p, n_nodes);
            biasinc_kernel<<<(n_nodes * D + 255) / 256, 256>>>(degt_p, be, bi_p, n_nodes);
            csr_fill<<<(E + 255) / 256, 256>>>(esrc, edst, etype, cursor_p, ebase_p, E);
        }
        aggregate<<<n_nodes, 160>>>(o1_p, bi_p, rowptr_p, ebase_p, inc_p);
        gemm_f16<<<g2, 256, GEMM_SMEM>>>(inc_p, f2h_p, f2m_p, gi_p, GILD, n_nodes, 450, bih);
        gru_kernel<<<(n_nodes * D + 255) / 256, 256>>>(gi_p, o1_p, h_p, n_nodes);
    }

    gstart_init<<<1, NG + 1>>>(gstart_p, n_nodes);
    gstart_min<<<(n_nodes + 255) / 256, 256>>>(gids, gstart_p, n_nodes);
    gstart_fix<<<1, 1>>>(gstart_p);
    readout<<<NG, 160>>>(h_p, gstart_p, pclass, x_p);
    mlp_kernel<<<NG, HIDN>>>(x_p, fc1w, fc1b, fc2w, fc2b, out);
}

// round 9
// speedup vs baseline: 2.6888x; 1.2342x over previous
#include <cuda_runtime.h>
#include <cuda_fp16.h>
#include <math.h>
#include <stdint.h>

#define NN 100000
#define NE 800000
#define NG 64
#define NT 4
#define D 150
#define HIDN 512
#define PASSES 5
#define NC1 1050
#define MLD 1056
#define GILD 456
#define XLD 152
#define NB1 9
#define NB2 4
#define NBM 782                    // ceil(100000/128) row blocks
#define FBLK (10 * 16 * 32 * 2)    // u32 per B column block
#define ABLK (10 * 8 * 128)        // u32 per A row block (10ks x 8mt x 32lane x 4reg)

__device__ float g_h[(size_t)NN * D];
__device__ float g_out1[(size_t)NN * MLD];
__device__ float g_gi[(size_t)NN * GILD];
__device__ float g_biasinc[(size_t)NN * D];
__device__ uint32_t g_Ah[(size_t)NBM * ABLK];   // h fragments (hi)
__device__ uint32_t g_Am[(size_t)NBM * ABLK];   // h fragments (mid)
__device__ uint32_t g_Ih[(size_t)NBM * ABLK];   // inc fragments (hi)
__device__ uint32_t g_Im[(size_t)NBM * ABLK];   // inc fragments (mid)
__device__ uint32_t g_F1h[NB1 * FBLK];
__device__ uint32_t g_F1m[NB1 * FBLK];
__device__ uint32_t g_F2h[NB2 * FBLK];
__device__ uint32_t g_F2m[NB2 * FBLK];
__device__ float g_bias1[NC1];
__device__ int   g_degt[NN * NT];
__device__ int   g_rowptr[NN + 1];
__device__ int   g_cursor[NN];
__device__ int   g_ebase[NE];
__device__ int   g_gstart[NG + 1];
__device__ float g_x[NG * XLD];

__device__ __forceinline__ uint32_t packh(float x0, float x1) {
    __half2 h = __floats2half2_rn(x0, x1);
    return *reinterpret_cast<uint32_t*>(&h);
}
__device__ __forceinline__ uint32_t split2(float x0, float x1, uint32_t* mid) {
    __half h0 = __float2half_rn(x0), h1 = __float2half_rn(x1);
    float m0 = x0 - __half2float(h0), m1 = x1 - __half2float(h1);
    *mid = packh(m0, m1);
    __half2 hh = __halves2half2(h0, h1);
    return *reinterpret_cast<uint32_t*>(&hh);
}
__device__ __forceinline__ void mma_f16(float* d, const uint32_t* a, const uint32_t* b) {
    asm volatile(
        "mma.sync.aligned.m16n8k16.row.col.f32.f16.f16.f32 "
        "{%0,%1,%2,%3}, {%4,%5,%6,%7}, {%8,%9}, {%0,%1,%2,%3};"
        : "+f"(d[0]), "+f"(d[1]), "+f"(d[2]), "+f"(d[3])
        : "r"(a[0]), "r"(a[1]), "r"(a[2]), "r"(a[3]), "r"(b[0]), "r"(b[1]));
}

// half-granular fragment index for A element (node, i); matches MMA A fragment map
__device__ __forceinline__ size_t frag_hidx(int node, int i) {
    int rb = node >> 7, mt = (node >> 4) & 7, r = node & 15;
    int ks = i >> 4, kk = i & 15, w = kk >> 1;
    int lane = (r & 7) * 4 + (w & 3);
    int reg = (r >> 3) + 2 * (w >> 2);
    size_t u32i = (((size_t)rb * 10 + ks) * 8 + mt) * 128 + lane * 4 + reg;
    return u32i * 2 + (i & 1);
}
// write split element to fragment arrays
__device__ __forceinline__ void frag_write(uint32_t* Fh, uint32_t* Fm, int node, int i, float v) {
    __half hi = __float2half_rn(v);
    __half mid = __float2half_rn(v - __half2float(hi));
    size_t fi = frag_hidx(node, i);
    ((__half*)Fh)[fi] = hi;
    ((__half*)Fm)[fi] = mid;
}

// ---------- setup: zero degt, fragment-ordered split weights, bias1 ----------
__global__ void setup_weights(const float* __restrict__ We, const float* __restrict__ whh,
                              const float* __restrict__ wih, const float* __restrict__ bhh,
                              uint32_t* __restrict__ F1h, uint32_t* __restrict__ F1m,
                              uint32_t* __restrict__ F2h, uint32_t* __restrict__ F2m,
                              float* __restrict__ bias1, int* __restrict__ degt) {
    int idx = blockIdx.x * blockDim.x + threadIdx.x;
    if (idx < NN * NT) { degt[idx] = 0; return; }
    idx -= NN * NT;
    if (idx < (NB1 + NB2) * FBLK) {
        int two = (idx >= NB1 * FBLK);
        int li = two ? idx - NB1 * FBLK : idx;
        int blk = li / FBLK, r = li % FBLK;
        int ks = r >> 10, r2 = r & 1023;
        int nt = r2 >> 6, r3 = r2 & 63;
        int lane = r3 >> 1, reg = r3 & 1;
        int n = blk * 128 + nt * 8 + (lane >> 2);
        int w = ks * 8 + reg * 4 + (lane & 3);
        int c0 = 2 * w, c1 = c0 + 1;
        float w0 = 0.f, w1 = 0.f;
        if (!two) {
            if (n < 600) {
                if (c0 < D) w0 = We[n * D + c0];
                if (c1 < D) w1 = We[n * D + c1];
            } else if (n < NC1) {
                if (c0 < D) w0 = whh[(n - 600) * D + c0];
                if (c1 < D) w1 = whh[(n - 600) * D + c1];
            }
        } else if (n < 450) {
            if (c0 < D) w0 = wih[n * D + c0];
            if (c1 < D) w1 = wih[n * D + c1];
        }
        uint32_t mid;
        uint32_t hi = split2(w0, w1, &mid);
        if (!two) { F1h[li] = hi; F1m[li] = mid; }
        else      { F2h[li] = hi; F2m[li] = mid; }
        return;
    }
    idx -= (NB1 + NB2) * FBLK;
    if (idx < NC1) bias1[idx] = (idx < 600) ? 0.f : bhh[idx - 600];
}

// copy nodes -> h (compact) and emit h fragments
__global__ void copy_h(const float* __restrict__ nodes, float* __restrict__ h,
                       uint32_t* __restrict__ Ah, uint32_t* __restrict__ Am,
                       int n_nodes) {
    int idx = blockIdx.x * blockDim.x + threadIdx.x;
    if (idx >= n_nodes * 160) return;
    int node = idx / 160, i = idx - node * 160;
    float v = 0.f;
    if (i < D) {
        v = nodes[node * D + i];
        h[node * D + i] = v;
    }
    frag_write(Ah, Am, node, i, v);
}

__global__ void hist_kernel(const int* __restrict__ dst, const int* __restrict__ etype,
                            int* __restrict__ degt, int E) {
    int e = blockIdx.x * blockDim.x + threadIdx.x;
    if (e < E) atomicAdd(&degt[dst[e] * NT + etype[e]], 1);
}

__global__ void biasinc_kernel(const int* __restrict__ degt, const float* __restrict__ be,
                               float* __restrict__ biasinc, int n_nodes) {
    int idx = blockIdx.x * blockDim.x + threadIdx.x;
    if (idx >= n_nodes * D) return;
    int node = idx / D, i = idx - node * D;
    float s = 0.f;
#pragma unroll
    for (int t = 0; t < NT; ++t) s += (float)degt[node * NT + t] * be[t * D + i];
    biasinc[idx] = s;
}

__global__ void scan_kernel(const int* __restrict__ degt, int* __restrict__ rowptr,
                            int* __restrict__ cursor, int n) {
    __shared__ int warp_tot[32];
    __shared__ int carry_s;
    int tid = threadIdx.x, lane = tid & 31, wid = tid >> 5;
    if (tid == 0) carry_s = 0;
    __syncthreads();
    for (int base = 0; base < n; base += 1024) {
        int idx = base + tid;
        int v = 0;
        if (idx < n)
            v = degt[idx * NT] + degt[idx * NT + 1] + degt[idx * NT + 2] + degt[idx * NT + 3];
        int x = v;
#pragma unroll
        for (int off = 1; off < 32; off <<= 1) {
            int y = __shfl_up_sync(0xffffffffu, x, off);
            if (lane >= off) x += y;
        }
        if (lane == 31) warp_tot[wid] = x;
        __syncthreads();
        if (wid == 0) {
            int w = warp_tot[lane], wx = w;
#pragma unroll
            for (int off = 1; off < 32; off <<= 1) {
                int y = __shfl_up_sync(0xffffffffu, wx, off);
                if (lane >= off) wx += y;
            }
            warp_tot[lane] = wx - w;
        }
        __syncthreads();
        int excl = carry_s + warp_tot[wid] + x - v;
        if (idx < n) { rowptr[idx] = excl; cursor[idx] = excl; }
        __syncthreads();
        if (tid == 1023) carry_s = excl + v;
        __syncthreads();
    }
    if (tid == 0) rowptr[n] = carry_s;
}

__global__ void csr_fill(const int* __restrict__ src, const int* __restrict__ dst,
                         const int* __restrict__ etype, int* __restrict__ cursor,
                         int* __restrict__ ebase, int E) {
    int e = blockIdx.x * blockDim.x + threadIdx.x;
    if (e >= E) return;
    int pos = atomicAdd(&cursor[dst[e]], 1);
    ebase[pos] = src[e] * MLD + etype[e] * D;
}

// ---------- fp16 3-split GEMM: all operands fragment-ordered in gmem, no smem
__global__ __launch_bounds__(256, 2) void gemm_f16(
    const uint32_t* __restrict__ Ah, const uint32_t* __restrict__ Am,
    const uint32_t* __restrict__ Fh, const uint32_t* __restrict__ Fm,
    float* __restrict__ C, int ldc, int M, int N,
    const float* __restrict__ bias) {
    int tid = threadIdx.x;
    int lane = tid & 31, wid = tid >> 5;
    int wm = wid & 1, wn = wid >> 1;
    int m0 = blockIdx.y * 128, n0 = blockIdx.x * 128;

    float acc[4][4][4];
#pragma unroll
    for (int i = 0; i < 4; ++i)
#pragma unroll
        for (int j = 0; j < 4; ++j)
#pragma unroll
            for (int r = 0; r < 4; ++r) acc[i][j][r] = 0.f;

    const uint32_t* abh = Ah + (size_t)blockIdx.y * ABLK;
    const uint32_t* abm = Am + (size_t)blockIdx.y * ABLK;
    const uint32_t* fbh = Fh + (size_t)blockIdx.x * FBLK;
    const uint32_t* fbm = Fm + (size_t)blockIdx.x * FBLK;

#pragma unroll
    for (int ks = 0; ks < 10; ++ks) {
        uint32_t ah[4][4], am[4][4], bh[4][2], bm[4][2];
#pragma unroll
        for (int mt = 0; mt < 4; ++mt) {
            size_t o = (((size_t)ks * 8) + wm * 4 + mt) * 128 + lane * 4;
            uint4 t = __ldg((const uint4*)(abh + o));
            ah[mt][0] = t.x; ah[mt][1] = t.y; ah[mt][2] = t.z; ah[mt][3] = t.w;
            uint4 u = __ldg((const uint4*)(abm + o));
            am[mt][0] = u.x; am[mt][1] = u.y; am[mt][2] = u.z; am[mt][3] = u.w;
        }
#pragma unroll
        for (int nt = 0; nt < 4; ++nt) {
            size_t o = (((size_t)ks * 16 + wn * 4 + nt) * 32 + lane) * 2;
            uint2 t = __ldg((const uint2*)(fbh + o));
            bh[nt][0] = t.x; bh[nt][1] = t.y;
            uint2 u = __ldg((const uint2*)(fbm + o));
            bm[nt][0] = u.x; bm[nt][1] = u.y;
        }
#pragma unroll
        for (int mt = 0; mt < 4; ++mt)
#pragma unroll
            for (int nt = 0; nt < 4; ++nt) {
                mma_f16(acc[mt][nt], ah[mt], bm[nt]);
                mma_f16(acc[mt][nt], am[mt], bh[nt]);
                mma_f16(acc[mt][nt], ah[mt], bh[nt]);
            }
    }

    int gi_ = lane >> 2, ti = lane & 3;
#pragma unroll
    for (int mt = 0; mt < 4; ++mt) {
#pragma unroll
        for (int nt = 0; nt < 4; ++nt) {
            int row = m0 + wm * 64 + mt * 16 + gi_;
            int col = n0 + wn * 32 + nt * 8 + 2 * ti;
            if (col >= N) continue;
            float b0 = bias[col], b1 = bias[col + 1];
            if (row < M) {
                float2 v = make_float2(acc[mt][nt][0] + b0, acc[mt][nt][1] + b1);
                *(float2*)&C[(size_t)row * ldc + col] = v;
            }
            if (row + 8 < M) {
                float2 v = make_float2(acc[mt][nt][2] + b0, acc[mt][nt][3] + b1);
                *(float2*)&C[(size_t)(row + 8) * ldc + col] = v;
            }
        }
    }
}

// ---------- CSR gather-aggregate, writes inc fragments directly ----------
__global__ void aggregate(const float* __restrict__ m, const float* __restrict__ biasinc,
                          const int* __restrict__ rowptr, const int* __restrict__ ebase,
                          uint32_t* __restrict__ Ih, uint32_t* __restrict__ Im) {
    int node = blockIdx.x;
    int i = threadIdx.x;   // 0..159
    float acc = 0.f;
    if (i < D) {
        int s = rowptr[node], e = rowptr[node + 1];
        acc = biasinc[(size_t)node * D + i];
        int p = s;
        for (; p + 3 < e; p += 4) {
            int b0 = ebase[p], b1 = ebase[p + 1], b2 = ebase[p + 2], b3 = ebase[p + 3];
            float v0 = m[(size_t)b0 + i];
            float v1 = m[(size_t)b1 + i];
            float v2 = m[(size_t)b2 + i];
            float v3 = m[(size_t)b3 + i];
            acc += (v0 + v1) + (v2 + v3);
        }
        for (; p < e; ++p) acc += m[(size_t)ebase[p] + i];
    }
    frag_write(Ih, Im, node, i, acc);
}

// ---------- GRU elementwise, writes h (compact) + h fragments ----------
__global__ void gru_kernel(const float* __restrict__ gi, const float* __restrict__ o1,
                           float* __restrict__ h,
                           uint32_t* __restrict__ Ah, uint32_t* __restrict__ Am,
                           int n_nodes) {
    int idx = blockIdx.x * blockDim.x + threadIdx.x;
    if (idx >= n_nodes * 160) return;
    int node = idx / 160, i = idx - node * 160;
    float nh = 0.f;
    if (i < D) {
        const float* gir = gi + (size_t)node * GILD;
        const float* ghr = o1 + (size_t)node * MLD + 600;
        float ir = gir[i], iz = gir[D + i], inn = gir[2 * D + i];
        float hr = ghr[i], hz = ghr[D + i], hn = ghr[2 * D + i];
        float r = 1.f / (1.f + expf(-(ir + hr)));
        float z = 1.f / (1.f + expf(-(iz + hz)));
        float nn = tanhf(inn + r * hn);
        size_t hidx = (size_t)node * D + i;
        nh = (1.f - z) * nn + z * h[hidx];
        h[hidx] = nh;
    }
    frag_write(Ah, Am, node, i, nh);
}

// ---------- readout + MLP ----------
__global__ void gstart_init(int* __restrict__ gstart, int n_nodes) {
    int g = threadIdx.x;
    if (g <= NG) gstart[g] = (g == NG) ? n_nodes : 0x7fffffff;
}
__global__ void gstart_min(const int* __restrict__ gids, int* __restrict__ gstart, int n) {
    int i = blockIdx.x * blockDim.x + threadIdx.x;
    if (i < n) atomicMin(&gstart[gids[i]], i);
}
__global__ void gstart_fix(int* __restrict__ gstart) {
    if (threadIdx.x == 0)
        for (int g = NG - 1; g >= 0; --g)
            if (gstart[g] == 0x7fffffff) gstart[g] = gstart[g + 1];
}
__global__ void readout(const float* __restrict__ h, const int* __restrict__ gstart,
                        const float* __restrict__ pclass, float* __restrict__ x) {
    int g = blockIdx.x, i = threadIdx.x;
    int s = gstart[g], e = gstart[g + 1];
    if (i < D) {
        float acc = 0.f;
        for (int n = s; n < e; ++n) acc += h[(size_t)n * D + i];
        float l = logf(acc);
        if (l != l) l = 0.f;
        l = fmaxf(l, 0.f);
        x[g * XLD + i] = l;
    }
    if (i == D) x[g * XLD + D] = pclass[g];
}
__global__ void mlp_kernel(const float* __restrict__ x,
                           const float* __restrict__ fc1w, const float* __restrict__ fc1b,
                           const float* __restrict__ fc2w, const float* __restrict__ fc2b,
                           float* __restrict__ out) {
    __shared__ float xb[D + 1];
    __shared__ float hid[HIDN];
    int g = blockIdx.x, t = threadIdx.x;
    if (t < D + 1) xb[t] = x[g * XLD + t];
    __syncthreads();
    float acc = fc1b[t];
    for (int k = 0; k < D + 1; ++k) acc += xb[k] * fc1w[k * HIDN + t];
    hid[t] = acc > 0.f ? acc : 0.01f * acc;
    __syncthreads();
    if (t < 10) {
        float o = fc2b[t];
        for (int k = 0; k < HIDN; ++k) o += hid[k] * fc2w[k * 10 + t];
        out[g * 10 + t] = o;
    }
}

// ---------- launch ----------
extern "C" void kernel_launch(void* const* d_in, const int* in_sizes, int n_in,
                              void* d_out, int out_size) {
    const float* nodes  = (const float*)d_in[0];
    const float* pclass = (const float*)d_in[1];
    const int*   esrc   = (const int*)d_in[2];
    const int*   edst   = (const int*)d_in[3];
    const int*   etype  = (const int*)d_in[4];
    const int*   gids   = (const int*)d_in[5];
    const float* We     = (const float*)d_in[6];
    const float* be     = (const float*)d_in[7];
    const float* wih    = (const float*)d_in[8];
    const float* whh    = (const float*)d_in[9];
    const float* bih    = (const float*)d_in[10];
    const float* bhh    = (const float*)d_in[11];
    const float* fc1w   = (const float*)d_in[12];
    const float* fc1b   = (const float*)d_in[13];
    const float* fc2w   = (const float*)d_in[14];
    const float* fc2b   = (const float*)d_in[15];
    float* out = (float*)d_out;

    int n_nodes = in_sizes[0] / D;
    int E = in_sizes[2];

    float *h_p, *o1_p, *gi_p, *bi_p, *b1_p, *x_p;
    uint32_t *ah_p, *am_p, *ih_p, *im_p, *f1h_p, *f1m_p, *f2h_p, *f2m_p;
    int *degt_p, *rowptr_p, *cursor_p, *ebase_p, *gstart_p;
    cudaGetSymbolAddress((void**)&h_p, g_h);
    cudaGetSymbolAddress((void**)&o1_p, g_out1);
    cudaGetSymbolAddress((void**)&gi_p, g_gi);
    cudaGetSymbolAddress((void**)&bi_p, g_biasinc);
    cudaGetSymbolAddress((void**)&ah_p, g_Ah);
    cudaGetSymbolAddress((void**)&am_p, g_Am);
    cudaGetSymbolAddress((void**)&ih_p, g_Ih);
    cudaGetSymbolAddress((void**)&im_p, g_Im);
    cudaGetSymbolAddress((void**)&f1h_p, g_F1h);
    cudaGetSymbolAddress((void**)&f1m_p, g_F1m);
    cudaGetSymbolAddress((void**)&f2h_p, g_F2h);
    cudaGetSymbolAddress((void**)&f2m_p, g_F2m);
    cudaGetSymbolAddress((void**)&b1_p, g_bias1);
    cudaGetSymbolAddress((void**)&x_p, g_x);
    cudaGetSymbolAddress((void**)&degt_p, g_degt);
    cudaGetSymbolAddress((void**)&rowptr_p, g_rowptr);
    cudaGetSymbolAddress((void**)&cursor_p, g_cursor);
    cudaGetSymbolAddress((void**)&ebase_p, g_ebase);
    cudaGetSymbolAddress((void**)&gstart_p, g_gstart);

    int setup_items = NN * NT + (NB1 + NB2) * FBLK + NC1;
    setup_weights<<<(setup_items + 255) / 256, 256>>>(We, whh, wih, bhh,
        f1h_p, f1m_p, f2h_p, f2m_p, b1_p, degt_p);
    copy_h<<<(n_nodes * 160 + 255) / 256, 256>>>(nodes, h_p, ah_p, am_p, n_nodes);
    hist_kernel<<<(E + 255) / 256, 256>>>(edst, etype, degt_p, E);

    int nby = (n_nodes + 127) / 128;
    dim3 g1(NB1, nby);
    dim3 g2(NB2, nby);

    for (int p = 0; p < PASSES; ++p) {
        gemm_f16<<<g1, 256>>>(ah_p, am_p, f1h_p, f1m_p, o1_p, MLD, n_nodes, NC1, b1_p);
        if (p == 0) {
            scan_kernel<<<1, 1024>>>(degt_p, rowptr_p, cursor_p, n_nodes);
            biasinc_kernel<<<(n_nodes * D + 255) / 256, 256>>>(degt_p, be, bi_p, n_nodes);
            csr_fill<<<(E + 255) / 256, 256>>>(esrc, edst, etype, cursor_p, ebase_p, E);
        }
        aggregate<<<n_nodes, 160>>>(o1_p, bi_p, rowptr_p, ebase_p, ih_p, im_p);
        gemm_f16<<<g2, 256>>>(ih_p, im_p, f2h_p, f2m_p, gi_p, GILD, n_nodes, 450, bih);
        gru_kernel<<<(n_nodes * 160 + 255) / 256, 256>>>(gi_p, o1_p, h_p, ah_p, am_p, n_nodes);
    }

    gstart_init<<<1, NG + 1>>>(gstart_p, n_nodes);
    gstart_min<<<(n_nodes + 255) / 256, 256>>>(gids, gstart_p, n_nodes);
    gstart_fix<<<1, 1>>>(gstart_p);
    readout<<<NG, 160>>>(h_p, gstart_p, pclass, x_p);
    mlp_kernel<<<NG, HIDN>>>(x_p, fc1w, fc1b, fc2w, fc2b, out);
}